// round 5
// baseline (speedup 1.0000x reference)
#include <cuda_runtime.h>
#include <math.h>

#define N_NODES 8192
#define NFEAT   512
#define NHID    256
#define NCLASS  40
#define CAP     64

// ---------------- scratch (static device globals; no runtime allocation) ----
__device__ int   g_nbr[N_NODES * CAP];   // 2 MB  neighbor column indices
__device__ int   g_cnt[N_NODES];         // per-row nonzero count (excl. eye)
__device__ float g_d[N_NODES];           // D^{-1/2}
__device__ float g_P1[N_NODES * NHID];   // 8 MB  x @ W1
__device__ float g_P2[N_NODES * NCLASS]; // 1.3MB relu(norm_adj@P1) @ W2

// ---------------------------------------------------------------------------
// Kernel 1: scan one adjacency row per block, compact nonzero columns.
// ---------------------------------------------------------------------------
__global__ __launch_bounds__(256) void build_sparse(const float* __restrict__ adj) {
    int row = blockIdx.x;
    int t   = threadIdx.x;
    const float4* arow = reinterpret_cast<const float4*>(adj + (size_t)row * N_NODES);

    unsigned mask = 0;
    #pragma unroll
    for (int i = 0; i < 8; i++) {
        float4 v = arow[i * 256 + t];
        if (v.x != 0.f) mask |= 1u << (i * 4 + 0);
        if (v.y != 0.f) mask |= 1u << (i * 4 + 1);
        if (v.z != 0.f) mask |= 1u << (i * 4 + 2);
        if (v.w != 0.f) mask |= 1u << (i * 4 + 3);
    }
    int c = __popc(mask);

    __shared__ int s[256];
    s[t] = c;
    __syncthreads();
    for (int off = 1; off < 256; off <<= 1) {        // inclusive scan
        int v = (t >= off) ? s[t - off] : 0;
        __syncthreads();
        s[t] += v;
        __syncthreads();
    }

    int base = row * CAP + (s[t] - c);               // exclusive offset
    unsigned m = mask;
    int k = 0;
    while (m) {
        int p = __ffs(m) - 1;
        m &= m - 1;
        int col = (((p >> 2) * 256 + t) << 2) + (p & 3);
        int slot = base + k;
        if (slot < row * CAP + CAP) g_nbr[slot] = col;   // safety clamp (never hit)
        k++;
    }
    if (t == 255) {
        int total = s[255];
        g_cnt[row] = (total > CAP) ? CAP : total;
        g_d[row]   = rsqrtf((float)(total + 1));     // +1 self loop
    }
}

// ---------------------------------------------------------------------------
// Kernel 2: g_P1 = x @ W1  [8192,512]x[512,256], fp32 64x64x16 tiling,
// register double-buffered global loads to hide k-tile latency.
// ---------------------------------------------------------------------------
#define BM 64
#define BN 64
#define BK 16
__global__ __launch_bounds__(256) void sgemm1(const float* __restrict__ A,
                                              const float* __restrict__ B) {
    const int Nn = NHID, K = NFEAT;
    __shared__ float As[BK][BM];
    __shared__ float Bs[BK][BN];

    int bx = blockIdx.x;          // N tile (0..3)
    int by = blockIdx.y;          // M tile (0..127)
    int tid = threadIdx.x;
    int tx = tid & 15, ty = tid >> 4;

    int arow = tid >> 2;          // 0..63
    int acol = (tid & 3) << 2;    // 0,4,8,12
    int brow = tid >> 4;          // 0..15
    int bcol = (tid & 15) << 2;   // 0..60

    const float* Aptr = A + (size_t)(by * BM + arow) * K + acol;
    const float* Bptr = B + (size_t)brow * Nn + bx * BN + bcol;

    float acc[4][4] = {};

    float4 av = *(const float4*)(Aptr);
    float4 bv = *(const float4*)(Bptr);

    for (int k0 = 0; k0 < K; k0 += BK) {
        As[acol + 0][arow] = av.x;
        As[acol + 1][arow] = av.y;
        As[acol + 2][arow] = av.z;
        As[acol + 3][arow] = av.w;
        *(float4*)&Bs[brow][bcol] = bv;
        __syncthreads();

        if (k0 + BK < K) {                      // prefetch next tile
            av = *(const float4*)(Aptr + k0 + BK);
            bv = *(const float4*)(Bptr + (size_t)(k0 + BK) * Nn);
        }

        #pragma unroll
        for (int k = 0; k < BK; k++) {
            float4 a = *(const float4*)&As[k][ty << 2];
            float4 b = *(const float4*)&Bs[k][tx << 2];
            acc[0][0] += a.x * b.x; acc[0][1] += a.x * b.y; acc[0][2] += a.x * b.z; acc[0][3] += a.x * b.w;
            acc[1][0] += a.y * b.x; acc[1][1] += a.y * b.y; acc[1][2] += a.y * b.z; acc[1][3] += a.y * b.w;
            acc[2][0] += a.z * b.x; acc[2][1] += a.z * b.y; acc[2][2] += a.z * b.z; acc[2][3] += a.z * b.w;
            acc[3][0] += a.w * b.x; acc[3][1] += a.w * b.y; acc[3][2] += a.w * b.z; acc[3][3] += a.w * b.w;
        }
        __syncthreads();
    }

    #pragma unroll
    for (int i = 0; i < 4; i++) {
        int r = by * BM + (ty << 2) + i;
        float4 o = make_float4(acc[i][0], acc[i][1], acc[i][2], acc[i][3]);
        *(float4*)(g_P1 + (size_t)r * Nn + bx * BN + (tx << 2)) = o;
    }
}

// ---------------------------------------------------------------------------
// Kernel 3 (FUSED spmm_relu + gemm2):
//   h[row,:]  = relu( d_i * ( sum_{j in nbr(i)} d_j*P1[j,:] + d_i*P1[i,:] ) )
//   P2[row,:] = h[row,:] @ W2          (h never leaves the block)
// One block (256 thr) per row. Warp w reduces classes [5w,5w+5) over k.
// ---------------------------------------------------------------------------
__global__ __launch_bounds__(256) void spmm_gemm2(const float* __restrict__ W2) {
    int row = blockIdx.x;
    int t   = threadIdx.x;
    __shared__ int   snbr[CAP];
    __shared__ float sd[CAP];
    __shared__ float sh[NHID];

    int cnt = g_cnt[row];
    if (t < cnt) { int j = g_nbr[row * CAP + t]; snbr[t] = j; sd[t] = g_d[j]; }
    __syncthreads();

    float di  = g_d[row];
    float acc = di * g_P1[(size_t)row * NHID + t];   // the +I (self-loop) term
    for (int k = 0; k < cnt; k++)
        acc += sd[k] * g_P1[(size_t)snbr[k] * NHID + t];
    sh[t] = fmaxf(di * acc, 0.f);
    __syncthreads();

    // h @ W2 : warp w -> classes [5w, 5w+5); lanes stride k; shfl reduce.
    int w = t >> 5, lane = t & 31;
    int c0 = w * 5;
    float a0 = 0.f, a1 = 0.f, a2 = 0.f, a3 = 0.f, a4 = 0.f;
    #pragma unroll
    for (int k = lane; k < NHID; k += 32) {
        float hv = sh[k];
        const float* w2r = W2 + k * NCLASS + c0;
        a0 += hv * w2r[0];
        a1 += hv * w2r[1];
        a2 += hv * w2r[2];
        a3 += hv * w2r[3];
        a4 += hv * w2r[4];
    }
    #pragma unroll
    for (int o = 16; o; o >>= 1) {
        a0 += __shfl_xor_sync(0xffffffffu, a0, o);
        a1 += __shfl_xor_sync(0xffffffffu, a1, o);
        a2 += __shfl_xor_sync(0xffffffffu, a2, o);
        a3 += __shfl_xor_sync(0xffffffffu, a3, o);
        a4 += __shfl_xor_sync(0xffffffffu, a4, o);
    }
    if (lane == 0) {
        float* p2 = g_P2 + (size_t)row * NCLASS + c0;
        p2[0] = a0; p2[1] = a1; p2[2] = a2; p2[3] = a3; p2[4] = a4;
    }
}

// ---------------------------------------------------------------------------
// Kernel 4: out = log_softmax( relu( norm_adj @ P2 ) ), one block (64thr)/row.
// ---------------------------------------------------------------------------
__global__ __launch_bounds__(64) void spmm2_out(float* __restrict__ out) {
    int row = blockIdx.x;
    int t   = threadIdx.x;   // 64 threads
    __shared__ int   snbr[CAP];
    __shared__ float sd[CAP];
    __shared__ float logits[NCLASS];
    __shared__ float red[2];

    int cnt = g_cnt[row];
    if (t < cnt) { int j = g_nbr[row * CAP + t]; snbr[t] = j; sd[t] = g_d[j]; }
    __syncthreads();

    float di = g_d[row];
    float v  = 0.f;
    if (t < NCLASS) {
        float acc = di * g_P2[(size_t)row * NCLASS + t];
        for (int k = 0; k < cnt; k++)
            acc += sd[k] * g_P2[(size_t)snbr[k] * NCLASS + t];
        v = fmaxf(di * acc, 0.f);
        logits[t] = v;
    }
    __syncthreads();

    if (t < 32) {
        float m = logits[t];
        if (t + 32 < NCLASS) m = fmaxf(m, logits[t + 32]);
        #pragma unroll
        for (int o = 16; o; o >>= 1) m = fmaxf(m, __shfl_xor_sync(0xffffffffu, m, o));
        if (t == 0) red[0] = m;
    }
    __syncthreads();
    float mx = red[0];
    if (t < 32) {
        float s2 = expf(logits[t] - mx);
        if (t + 32 < NCLASS) s2 += expf(logits[t + 32] - mx);
        #pragma unroll
        for (int o = 16; o; o >>= 1) s2 += __shfl_xor_sync(0xffffffffu, s2, o);
        if (t == 0) red[1] = s2;
    }
    __syncthreads();
    if (t < NCLASS)
        out[(size_t)row * NCLASS + t] = v - mx - logf(red[1]);
}

// ---------------------------------------------------------------------------
// Launch DAG:   sgemm1 ──────────┐
//               build_sparse ────┴─> spmm_gemm2 -> spmm2_out
// build_sparse (DRAM-bound) forked onto a side stream so it overlaps the
// FMA-bound sgemm1. Host-side stream/event create+destroy only runs on the
// correctness + capture calls; graph replays pay nothing.
// ---------------------------------------------------------------------------
extern "C" void kernel_launch(void* const* d_in, const int* in_sizes, int n_in,
                              void* d_out, int out_size) {
    const float* x   = (const float*)d_in[0];   // [8192, 512]
    const float* adj = (const float*)d_in[1];   // [8192, 8192]
    const float* W1  = (const float*)d_in[2];   // [512, 256]
    const float* W2  = (const float*)d_in[3];   // [256, 40]
    float* out = (float*)d_out;                 // [8192, 40]

    cudaStream_t s2;
    cudaEvent_t eFork, eJoin;
    cudaStreamCreateWithFlags(&s2, cudaStreamNonBlocking);
    cudaEventCreateWithFlags(&eFork, cudaEventDisableTiming);
    cudaEventCreateWithFlags(&eJoin, cudaEventDisableTiming);

    cudaEventRecord(eFork, 0);                 // fork off the captured stream
    cudaStreamWaitEvent(s2, eFork, 0);
    build_sparse<<<N_NODES, 256, 0, s2>>>(adj);
    cudaEventRecord(eJoin, s2);

    sgemm1<<<dim3(NHID / BN, N_NODES / BM), 256>>>(x, W1);

    cudaStreamWaitEvent(0, eJoin, 0);          // join before the SpMM
    spmm_gemm2<<<N_NODES, 256>>>(W2);
    spmm2_out<<<N_NODES, 64>>>(out);

    cudaEventDestroy(eFork);
    cudaEventDestroy(eJoin);
    cudaStreamDestroy(s2);
}

// round 7
// speedup vs baseline: 1.1697x; 1.1697x over previous
#include <cuda_runtime.h>
#include <cuda_bf16.h>
#include <math.h>
#include <cstdint>

#define N_NODES 8192
#define NFEAT   512
#define NHID    256
#define NCLASS  40
#define CAP     64

// ---------------- scratch (static device globals; no runtime allocation) ----
__device__ int   g_nbr[N_NODES * CAP];
__device__ int   g_cnt[N_NODES];
__device__ float g_d[N_NODES];
__device__ float g_P1[N_NODES * NHID];            // x @ W1 (fp32 result)
__device__ float g_P2[N_NODES * NCLASS];
__device__ __nv_bfloat16 g_xhi[N_NODES * NFEAT];  // 8 MB
__device__ __nv_bfloat16 g_xlo[N_NODES * NFEAT];  // 8 MB
__device__ __nv_bfloat16 g_w1hi[NHID * NFEAT];    // W1^T, [n][k], 256 KB
__device__ __nv_bfloat16 g_w1lo[NHID * NFEAT];

// ======================= helpers (base-target PTX only) =====================
__device__ __forceinline__ uint32_t smem_u32(const void* p) {
    uint32_t a;
    asm("{ .reg .u64 t; cvta.to.shared.u64 t, %1; cvt.u32.u64 %0, t; }" : "=r"(a) : "l"(p));
    return a;
}
#define CP_ASYNC16(dst, src) \
    asm volatile("cp.async.cg.shared.global [%0], [%1], 16;" :: "r"(dst), "l"(src))
#define CP_COMMIT()  asm volatile("cp.async.commit_group;" ::: "memory")
#define CP_WAIT1()   asm volatile("cp.async.wait_group 1;" ::: "memory")
#define CP_WAIT0()   asm volatile("cp.async.wait_group 0;" ::: "memory")
#define LDSM_X4(r0, r1, r2, r3, a) \
    asm volatile("ldmatrix.sync.aligned.m8n8.x4.shared.b16 {%0,%1,%2,%3}, [%4];" \
                 : "=r"(r0), "=r"(r1), "=r"(r2), "=r"(r3) : "r"(a))
#define MMA_BF16(d, a, b) \
    asm volatile("mma.sync.aligned.m16n8k16.row.col.f32.bf16.bf16.f32 " \
                 "{%0,%1,%2,%3}, {%4,%5,%6,%7}, {%8,%9}, {%0,%1,%2,%3};" \
                 : "+f"((d)[0]), "+f"((d)[1]), "+f"((d)[2]), "+f"((d)[3]) \
                 : "r"((a)[0]), "r"((a)[1]), "r"((a)[2]), "r"((a)[3]), \
                   "r"((b)[0]), "r"((b)[1]))

// ---------------------------------------------------------------------------
// Kernel 1: adjacency scan -> compact neighbor lists + D^{-1/2}. (unchanged)
// ---------------------------------------------------------------------------
__global__ __launch_bounds__(256) void build_sparse(const float* __restrict__ adj) {
    int row = blockIdx.x;
    int t   = threadIdx.x;
    const float4* arow = reinterpret_cast<const float4*>(adj + (size_t)row * N_NODES);

    unsigned mask = 0;
    #pragma unroll
    for (int i = 0; i < 8; i++) {
        float4 v = arow[i * 256 + t];
        if (v.x != 0.f) mask |= 1u << (i * 4 + 0);
        if (v.y != 0.f) mask |= 1u << (i * 4 + 1);
        if (v.z != 0.f) mask |= 1u << (i * 4 + 2);
        if (v.w != 0.f) mask |= 1u << (i * 4 + 3);
    }
    int c = __popc(mask);

    __shared__ int s[256];
    s[t] = c;
    __syncthreads();
    for (int off = 1; off < 256; off <<= 1) {
        int v = (t >= off) ? s[t - off] : 0;
        __syncthreads();
        s[t] += v;
        __syncthreads();
    }

    int base = row * CAP + (s[t] - c);
    unsigned m = mask;
    int k = 0;
    while (m) {
        int p = __ffs(m) - 1;
        m &= m - 1;
        int col = (((p >> 2) * 256 + t) << 2) + (p & 3);
        int slot = base + k;
        if (slot < row * CAP + CAP) g_nbr[slot] = col;
        k++;
    }
    if (t == 255) {
        int total = s[255];
        g_cnt[row] = (total > CAP) ? CAP : total;
        g_d[row]   = rsqrtf((float)(total + 1));
    }
}

// ---------------------------------------------------------------------------
// Kernel 2a: split x into bf16 hi/lo (x = hi + lo to ~16 mantissa bits).
// ---------------------------------------------------------------------------
__global__ __launch_bounds__(256) void cvt_x(const float* __restrict__ x) {
    size_t i = (size_t)blockIdx.x * 256 + threadIdx.x;
    float4 v = reinterpret_cast<const float4*>(x)[i];
    __nv_bfloat16 h0 = __float2bfloat16(v.x), h1 = __float2bfloat16(v.y);
    __nv_bfloat16 h2 = __float2bfloat16(v.z), h3 = __float2bfloat16(v.w);
    __nv_bfloat16 l0 = __float2bfloat16(v.x - __bfloat162float(h0));
    __nv_bfloat16 l1 = __float2bfloat16(v.y - __bfloat162float(h1));
    __nv_bfloat16 l2 = __float2bfloat16(v.z - __bfloat162float(h2));
    __nv_bfloat16 l3 = __float2bfloat16(v.w - __bfloat162float(h3));
    uint2 ph, pl;
    ph.x = (uint32_t)__bfloat16_as_ushort(h0) | ((uint32_t)__bfloat16_as_ushort(h1) << 16);
    ph.y = (uint32_t)__bfloat16_as_ushort(h2) | ((uint32_t)__bfloat16_as_ushort(h3) << 16);
    pl.x = (uint32_t)__bfloat16_as_ushort(l0) | ((uint32_t)__bfloat16_as_ushort(l1) << 16);
    pl.y = (uint32_t)__bfloat16_as_ushort(l2) | ((uint32_t)__bfloat16_as_ushort(l3) << 16);
    reinterpret_cast<uint2*>(g_xhi)[i] = ph;
    reinterpret_cast<uint2*>(g_xlo)[i] = pl;
}

// Kernel 2b: W1 [512,256] -> transposed K-major hi/lo [n][k].
__global__ __launch_bounds__(512) void cvt_w1(const float* __restrict__ W1) {
    int n = blockIdx.x;       // 0..255
    int k = threadIdx.x;      // 0..511
    float v = W1[(size_t)k * NHID + n];
    __nv_bfloat16 h = __float2bfloat16(v);
    __nv_bfloat16 l = __float2bfloat16(v - __bfloat162float(h));
    g_w1hi[(size_t)n * NFEAT + k] = h;
    g_w1lo[(size_t)n * NFEAT + k] = l;
}

// ---------------------------------------------------------------------------
// Kernel 3: g_P1 = x @ W1 via mma.sync bf16 (hi/lo compensated, fp32 accum).
// Block tile 128x128x32, 8 warps (4M x 2N), warp tile 32x64 = 2x8 m16n8k16.
// cp.async double-buffered stages; padded smem rows (40 bf16 = 80B) make the
// 8 ldmatrix row-addresses tile all 32 banks (0,80,160.. mod 128 distinct).
// ---------------------------------------------------------------------------
#define BKT   32
#define LDA   40                                  // bf16 stride (80 B)
#define TILE_B (128 * LDA * 2)                    // 10240 B per tile
#define STG_B  (4 * TILE_B)                       // Ahi|Alo|Bhi|Blo = 40960 B
#define SMEM_MMA (2 * STG_B)                      // 81920 B

__global__ __launch_bounds__(256, 1) void mma_gemm1() {
    extern __shared__ char smem[];
    uint32_t sb = smem_u32(smem);
    int tid = threadIdx.x, lane = tid & 31, wid = tid >> 5;
    int wm = wid & 3, wn = wid >> 2;              // 4 x 2 warp grid
    int bx = blockIdx.x, by = blockIdx.y;
    int m_blk = by * 128, n_blk = bx * 128;

    // per-thread cp.async chunk coords: q in {tid, tid+256}; r=q>>2, c=q&3
    int r0 = tid >> 2, c0 = (tid & 3);
    int r1 = (tid + 256) >> 2, c1 = c0;           // q+256 keeps c, r += 64
    const __nv_bfloat16* srcA_h = g_xhi  + (size_t)(m_blk + r0) * NFEAT + c0 * 8;
    const __nv_bfloat16* srcA_l = g_xlo  + (size_t)(m_blk + r0) * NFEAT + c0 * 8;
    const __nv_bfloat16* srcB_h = g_w1hi + (size_t)(n_blk + r0) * NFEAT + c0 * 8;
    const __nv_bfloat16* srcB_l = g_w1lo + (size_t)(n_blk + r0) * NFEAT + c0 * 8;
    uint32_t dst0 = r0 * (LDA * 2) + c0 * 16;
    uint32_t dst1 = r1 * (LDA * 2) + c1 * 16;
    const size_t rowskip = (size_t)64 * NFEAT;    // r -> r+64

    float acc[2][8][4] = {};

    // ldmatrix lane-address components
    uint32_t a_r  = (lane & 15);                  // A row within 16
    uint32_t a_k  = (lane >> 4) * 16;             // A k-half byte offset
    uint32_t b_r  = ((lane >> 4) & 1) * 8 + (lane & 7);
    uint32_t b_k  = ((lane >> 3) & 1) * 16;

    #define ISSUE_STAGE(it, stg) do {                                           \
        uint32_t s0 = sb + (stg) * STG_B;                                       \
        size_t ko = (size_t)(it) * BKT;                                         \
        CP_ASYNC16(s0 + dst0,              srcA_h + ko);                        \
        CP_ASYNC16(s0 + dst1,              srcA_h + ko + rowskip);              \
        CP_ASYNC16(s0 + TILE_B + dst0,     srcA_l + ko);                        \
        CP_ASYNC16(s0 + TILE_B + dst1,     srcA_l + ko + rowskip);              \
        CP_ASYNC16(s0 + 2 * TILE_B + dst0, srcB_h + ko);                        \
        CP_ASYNC16(s0 + 2 * TILE_B + dst1, srcB_h + ko + rowskip);              \
        CP_ASYNC16(s0 + 3 * TILE_B + dst0, srcB_l + ko);                        \
        CP_ASYNC16(s0 + 3 * TILE_B + dst1, srcB_l + ko + rowskip);              \
    } while (0)

    ISSUE_STAGE(0, 0);
    CP_COMMIT();

    const int NIT = NFEAT / BKT;                  // 16
    for (int it = 0; it < NIT; it++) {
        int stg = it & 1;
        if (it + 1 < NIT) { ISSUE_STAGE(it + 1, stg ^ 1); CP_COMMIT(); CP_WAIT1(); }
        else              { CP_WAIT0(); }
        __syncthreads();

        uint32_t sA = sb + stg * STG_B;
        uint32_t sB = sA + 2 * TILE_B;
        #pragma unroll
        for (int ks = 0; ks < 2; ks++) {
            uint32_t kofs = ks * 32;              // 16 bf16 = 32 B
            uint32_t ah[2][4], al[2][4], bh[8][2], bl[8][2];
            #pragma unroll
            for (int mf = 0; mf < 2; mf++) {
                uint32_t addr = sA + (wm * 32 + mf * 16 + a_r) * (LDA * 2) + a_k + kofs;
                LDSM_X4(ah[mf][0], ah[mf][1], ah[mf][2], ah[mf][3], addr);
                LDSM_X4(al[mf][0], al[mf][1], al[mf][2], al[mf][3], addr + TILE_B);
            }
            #pragma unroll
            for (int np = 0; np < 4; np++) {
                uint32_t addr = sB + (wn * 64 + np * 16 + b_r) * (LDA * 2) + b_k + kofs;
                uint32_t t0, t1, t2, t3;
                LDSM_X4(t0, t1, t2, t3, addr);
                bh[2 * np][0] = t0; bh[2 * np][1] = t1;
                bh[2 * np + 1][0] = t2; bh[2 * np + 1][1] = t3;
                LDSM_X4(t0, t1, t2, t3, addr + TILE_B);
                bl[2 * np][0] = t0; bl[2 * np][1] = t1;
                bl[2 * np + 1][0] = t2; bl[2 * np + 1][1] = t3;
            }
            #pragma unroll
            for (int mf = 0; mf < 2; mf++)
                #pragma unroll
                for (int nf = 0; nf < 8; nf++) {
                    MMA_BF16(acc[mf][nf], ah[mf], bh[nf]);
                    MMA_BF16(acc[mf][nf], ah[mf], bl[nf]);
                    MMA_BF16(acc[mf][nf], al[mf], bh[nf]);
                }
        }
        __syncthreads();
    }

    // epilogue: d0,d1 -> (row, col..col+1); d2,d3 -> (row+8, col..col+1)
    int rr = m_blk + wm * 32 + (lane >> 2);
    int cc = n_blk + wn * 64 + 2 * (lane & 3);
    #pragma unroll
    for (int mf = 0; mf < 2; mf++)
        #pragma unroll
        for (int nf = 0; nf < 8; nf++) {
            float* d0 = g_P1 + (size_t)(rr + mf * 16) * NHID + cc + nf * 8;
            float* d1 = g_P1 + (size_t)(rr + mf * 16 + 8) * NHID + cc + nf * 8;
            *reinterpret_cast<float2*>(d0) = make_float2(acc[mf][nf][0], acc[mf][nf][1]);
            *reinterpret_cast<float2*>(d1) = make_float2(acc[mf][nf][2], acc[mf][nf][3]);
        }
}

// ---------------------------------------------------------------------------
// Kernel 4 (fused spmm_relu + gemm2): P2 = relu(norm_adj @ P1) @ W2.
// ---------------------------------------------------------------------------
__global__ __launch_bounds__(256) void spmm_gemm2(const float* __restrict__ W2) {
    int row = blockIdx.x;
    int t   = threadIdx.x;
    __shared__ int   snbr[CAP];
    __shared__ float sd[CAP];
    __shared__ float sh[NHID];

    int cnt = g_cnt[row];
    if (t < cnt) { int j = g_nbr[row * CAP + t]; snbr[t] = j; sd[t] = g_d[j]; }
    __syncthreads();

    float di  = g_d[row];
    float acc = di * g_P1[(size_t)row * NHID + t];
    for (int k = 0; k < cnt; k++)
        acc += sd[k] * g_P1[(size_t)snbr[k] * NHID + t];
    sh[t] = fmaxf(di * acc, 0.f);
    __syncthreads();

    int w = t >> 5, lane = t & 31;
    int c0 = w * 5;
    float a0 = 0.f, a1 = 0.f, a2 = 0.f, a3 = 0.f, a4 = 0.f;
    #pragma unroll
    for (int k = lane; k < NHID; k += 32) {
        float hv = sh[k];
        const float* w2r = W2 + k * NCLASS + c0;
        a0 += hv * w2r[0];
        a1 += hv * w2r[1];
        a2 += hv * w2r[2];
        a3 += hv * w2r[3];
        a4 += hv * w2r[4];
    }
    #pragma unroll
    for (int o = 16; o; o >>= 1) {
        a0 += __shfl_xor_sync(0xffffffffu, a0, o);
        a1 += __shfl_xor_sync(0xffffffffu, a1, o);
        a2 += __shfl_xor_sync(0xffffffffu, a2, o);
        a3 += __shfl_xor_sync(0xffffffffu, a3, o);
        a4 += __shfl_xor_sync(0xffffffffu, a4, o);
    }
    if (lane == 0) {
        float* p2 = g_P2 + (size_t)row * NCLASS + c0;
        p2[0] = a0; p2[1] = a1; p2[2] = a2; p2[3] = a3; p2[4] = a4;
    }
}

// ---------------------------------------------------------------------------
// Kernel 5: out = log_softmax( relu( norm_adj @ P2 ) ).
// ---------------------------------------------------------------------------
__global__ __launch_bounds__(64) void spmm2_out(float* __restrict__ out) {
    int row = blockIdx.x;
    int t   = threadIdx.x;
    __shared__ int   snbr[CAP];
    __shared__ float sd[CAP];
    __shared__ float logits[NCLASS];
    __shared__ float red[2];

    int cnt = g_cnt[row];
    if (t < cnt) { int j = g_nbr[row * CAP + t]; snbr[t] = j; sd[t] = g_d[j]; }
    __syncthreads();

    float di = g_d[row];
    float v  = 0.f;
    if (t < NCLASS) {
        float acc = di * g_P2[(size_t)row * NCLASS + t];
        for (int k = 0; k < cnt; k++)
            acc += sd[k] * g_P2[(size_t)snbr[k] * NCLASS + t];
        v = fmaxf(di * acc, 0.f);
        logits[t] = v;
    }
    __syncthreads();

    if (t < 32) {
        float m = logits[t];
        if (t + 32 < NCLASS) m = fmaxf(m, logits[t + 32]);
        #pragma unroll
        for (int o = 16; o; o >>= 1) m = fmaxf(m, __shfl_xor_sync(0xffffffffu, m, o));
        if (t == 0) red[0] = m;
    }
    __syncthreads();
    float mx = red[0];
    if (t < 32) {
        float s2 = expf(logits[t] - mx);
        if (t + 32 < NCLASS) s2 += expf(logits[t + 32] - mx);
        #pragma unroll
        for (int o = 16; o; o >>= 1) s2 += __shfl_xor_sync(0xffffffffu, s2, o);
        if (t == 0) red[1] = s2;
    }
    __syncthreads();
    if (t < NCLASS)
        out[(size_t)row * NCLASS + t] = v - mx - logf(red[1]);
}

// ---------------------------------------------------------------------------
// Serial launch (overlap regressed in R5; tcgen05 blocked by compute_103 PTX).
// ---------------------------------------------------------------------------
extern "C" void kernel_launch(void* const* d_in, const int* in_sizes, int n_in,
                              void* d_out, int out_size) {
    const float* x   = (const float*)d_in[0];   // [8192, 512]
    const float* adj = (const float*)d_in[1];   // [8192, 8192]
    const float* W1  = (const float*)d_in[2];   // [512, 256]
    const float* W2  = (const float*)d_in[3];   // [256, 40]
    float* out = (float*)d_out;                 // [8192, 40]

    cudaFuncSetAttribute(mma_gemm1, cudaFuncAttributeMaxDynamicSharedMemorySize, SMEM_MMA);

    build_sparse<<<N_NODES, 256>>>(adj);
    cvt_x<<<(N_NODES * NFEAT) / (4 * 256), 256>>>(x);
    cvt_w1<<<NHID, 512>>>(W1);
    mma_gemm1<<<dim3(NHID / 128, N_NODES / 128), 256, SMEM_MMA>>>();
    spmm_gemm2<<<N_NODES, 256>>>(W2);
    spmm2_out<<<N_NODES, 64>>>(out);
}

// round 8
// speedup vs baseline: 1.6584x; 1.4178x over previous
#include <cuda_runtime.h>
#include <cuda_bf16.h>
#include <math.h>
#include <cstdint>

#define N_NODES 8192
#define NFEAT   512
#define NHID    256
#define NCLASS  40
#define CAP     64

// ---------------- scratch (static device globals; no runtime allocation) ----
__device__ int   g_nbr[N_NODES * CAP];
__device__ int   g_cnt[N_NODES];
__device__ float g_d[N_NODES];
__device__ float g_P1[N_NODES * NHID];            // x @ W1 (fp32 result)
__device__ float g_P2[N_NODES * NCLASS];
__device__ float g_W2T[NCLASS * NHID];            // W2 transposed [class][k], 40 KB
__device__ __nv_bfloat16 g_xhi[N_NODES * NFEAT];  // 8 MB
__device__ __nv_bfloat16 g_xlo[N_NODES * NFEAT];  // 8 MB
__device__ __nv_bfloat16 g_w1hi[NHID * NFEAT];    // W1^T, [n][k], 256 KB
__device__ __nv_bfloat16 g_w1lo[NHID * NFEAT];

// ======================= helpers (base-target PTX only) =====================
__device__ __forceinline__ uint32_t smem_u32(const void* p) {
    uint32_t a;
    asm("{ .reg .u64 t; cvta.to.shared.u64 t, %1; cvt.u32.u64 %0, t; }" : "=r"(a) : "l"(p));
    return a;
}
#define CP_ASYNC16(dst, src) \
    asm volatile("cp.async.cg.shared.global [%0], [%1], 16;" :: "r"(dst), "l"(src))
#define CP_COMMIT()  asm volatile("cp.async.commit_group;" ::: "memory")
#define CP_WAIT1()   asm volatile("cp.async.wait_group 1;" ::: "memory")
#define CP_WAIT0()   asm volatile("cp.async.wait_group 0;" ::: "memory")
#define LDSM_X4(r0, r1, r2, r3, a) \
    asm volatile("ldmatrix.sync.aligned.m8n8.x4.shared.b16 {%0,%1,%2,%3}, [%4];" \
                 : "=r"(r0), "=r"(r1), "=r"(r2), "=r"(r3) : "r"(a))
#define MMA_BF16(d, a, b) \
    asm volatile("mma.sync.aligned.m16n8k16.row.col.f32.bf16.bf16.f32 " \
                 "{%0,%1,%2,%3}, {%4,%5,%6,%7}, {%8,%9}, {%0,%1,%2,%3};" \
                 : "+f"((d)[0]), "+f"((d)[1]), "+f"((d)[2]), "+f"((d)[3]) \
                 : "r"((a)[0]), "r"((a)[1]), "r"((a)[2]), "r"((a)[3]), \
                   "r"((b)[0]), "r"((b)[1]))

// ---------------------------------------------------------------------------
// Kernel 1: adjacency scan -> compact neighbor lists + D^{-1/2}. (unchanged)
// ---------------------------------------------------------------------------
__global__ __launch_bounds__(256) void build_sparse(const float* __restrict__ adj) {
    int row = blockIdx.x;
    int t   = threadIdx.x;
    const float4* arow = reinterpret_cast<const float4*>(adj + (size_t)row * N_NODES);

    unsigned mask = 0;
    #pragma unroll
    for (int i = 0; i < 8; i++) {
        float4 v = arow[i * 256 + t];
        if (v.x != 0.f) mask |= 1u << (i * 4 + 0);
        if (v.y != 0.f) mask |= 1u << (i * 4 + 1);
        if (v.z != 0.f) mask |= 1u << (i * 4 + 2);
        if (v.w != 0.f) mask |= 1u << (i * 4 + 3);
    }
    int c = __popc(mask);

    __shared__ int s[256];
    s[t] = c;
    __syncthreads();
    for (int off = 1; off < 256; off <<= 1) {
        int v = (t >= off) ? s[t - off] : 0;
        __syncthreads();
        s[t] += v;
        __syncthreads();
    }

    int base = row * CAP + (s[t] - c);
    unsigned m = mask;
    int k = 0;
    while (m) {
        int p = __ffs(m) - 1;
        m &= m - 1;
        int col = (((p >> 2) * 256 + t) << 2) + (p & 3);
        int slot = base + k;
        if (slot < row * CAP + CAP) g_nbr[slot] = col;
        k++;
    }
    if (t == 255) {
        int total = s[255];
        g_cnt[row] = (total > CAP) ? CAP : total;
        g_d[row]   = rsqrtf((float)(total + 1));
    }
}

// ---------------------------------------------------------------------------
// Kernel 2a: split x into bf16 hi/lo (x = hi + lo to ~16 mantissa bits).
// ---------------------------------------------------------------------------
__global__ __launch_bounds__(256) void cvt_x(const float* __restrict__ x) {
    size_t i = (size_t)blockIdx.x * 256 + threadIdx.x;
    float4 v = reinterpret_cast<const float4*>(x)[i];
    __nv_bfloat16 h0 = __float2bfloat16(v.x), h1 = __float2bfloat16(v.y);
    __nv_bfloat16 h2 = __float2bfloat16(v.z), h3 = __float2bfloat16(v.w);
    __nv_bfloat16 l0 = __float2bfloat16(v.x - __bfloat162float(h0));
    __nv_bfloat16 l1 = __float2bfloat16(v.y - __bfloat162float(h1));
    __nv_bfloat16 l2 = __float2bfloat16(v.z - __bfloat162float(h2));
    __nv_bfloat16 l3 = __float2bfloat16(v.w - __bfloat162float(h3));
    uint2 ph, pl;
    ph.x = (uint32_t)__bfloat16_as_ushort(h0) | ((uint32_t)__bfloat16_as_ushort(h1) << 16);
    ph.y = (uint32_t)__bfloat16_as_ushort(h2) | ((uint32_t)__bfloat16_as_ushort(h3) << 16);
    pl.x = (uint32_t)__bfloat16_as_ushort(l0) | ((uint32_t)__bfloat16_as_ushort(l1) << 16);
    pl.y = (uint32_t)__bfloat16_as_ushort(l2) | ((uint32_t)__bfloat16_as_ushort(l3) << 16);
    reinterpret_cast<uint2*>(g_xhi)[i] = ph;
    reinterpret_cast<uint2*>(g_xlo)[i] = pl;
}

// Kernel 2b: W1 [512,256] -> transposed K-major hi/lo [n][k].
__global__ __launch_bounds__(512) void cvt_w1(const float* __restrict__ W1) {
    int n = blockIdx.x;       // 0..255
    int k = threadIdx.x;      // 0..511
    float v = W1[(size_t)k * NHID + n];
    __nv_bfloat16 h = __float2bfloat16(v);
    __nv_bfloat16 l = __float2bfloat16(v - __bfloat162float(h));
    g_w1hi[(size_t)n * NFEAT + k] = h;
    g_w1lo[(size_t)n * NFEAT + k] = l;
}

// Kernel 2c: W2 [256,40] -> transposed [40][256] so the spmm_gemm2 epilogue
// reads coalesced 128B lines instead of 160B-strided scatter (32 wavefronts
// per LDG was the R7 bottleneck).
__global__ __launch_bounds__(256) void cvt_w2t(const float* __restrict__ W2) {
    for (int i = threadIdx.x; i < NHID * NCLASS; i += 256) {
        int k = i / NCLASS, c = i % NCLASS;
        g_W2T[(size_t)c * NHID + k] = W2[i];
    }
}

// ---------------------------------------------------------------------------
// Kernel 3: g_P1 = x @ W1 via mma.sync bf16 (hi/lo compensated, fp32 accum).
// (unchanged from R7: 27.4us, tensor 37.9%)
// ---------------------------------------------------------------------------
#define BKT   32
#define LDA   40                                  // bf16 stride (80 B)
#define TILE_B (128 * LDA * 2)                    // 10240 B per tile
#define STG_B  (4 * TILE_B)                       // Ahi|Alo|Bhi|Blo = 40960 B
#define SMEM_MMA (2 * STG_B)                      // 81920 B

__global__ __launch_bounds__(256, 1) void mma_gemm1() {
    extern __shared__ char smem[];
    uint32_t sb = smem_u32(smem);
    int tid = threadIdx.x, lane = tid & 31, wid = tid >> 5;
    int wm = wid & 3, wn = wid >> 2;              // 4 x 2 warp grid
    int bx = blockIdx.x, by = blockIdx.y;
    int m_blk = by * 128, n_blk = bx * 128;

    int r0 = tid >> 2, c0 = (tid & 3);
    int r1 = (tid + 256) >> 2, c1 = c0;
    const __nv_bfloat16* srcA_h = g_xhi  + (size_t)(m_blk + r0) * NFEAT + c0 * 8;
    const __nv_bfloat16* srcA_l = g_xlo  + (size_t)(m_blk + r0) * NFEAT + c0 * 8;
    const __nv_bfloat16* srcB_h = g_w1hi + (size_t)(n_blk + r0) * NFEAT + c0 * 8;
    const __nv_bfloat16* srcB_l = g_w1lo + (size_t)(n_blk + r0) * NFEAT + c0 * 8;
    uint32_t dst0 = r0 * (LDA * 2) + c0 * 16;
    uint32_t dst1 = r1 * (LDA * 2) + c1 * 16;
    const size_t rowskip = (size_t)64 * NFEAT;

    float acc[2][8][4] = {};

    uint32_t a_r  = (lane & 15);
    uint32_t a_k  = (lane >> 4) * 16;
    uint32_t b_r  = ((lane >> 4) & 1) * 8 + (lane & 7);
    uint32_t b_k  = ((lane >> 3) & 1) * 16;

    #define ISSUE_STAGE(it, stg) do {                                           \
        uint32_t s0 = sb + (stg) * STG_B;                                       \
        size_t ko = (size_t)(it) * BKT;                                         \
        CP_ASYNC16(s0 + dst0,              srcA_h + ko);                        \
        CP_ASYNC16(s0 + dst1,              srcA_h + ko + rowskip);              \
        CP_ASYNC16(s0 + TILE_B + dst0,     srcA_l + ko);                        \
        CP_ASYNC16(s0 + TILE_B + dst1,     srcA_l + ko + rowskip);              \
        CP_ASYNC16(s0 + 2 * TILE_B + dst0, srcB_h + ko);                        \
        CP_ASYNC16(s0 + 2 * TILE_B + dst1, srcB_h + ko + rowskip);              \
        CP_ASYNC16(s0 + 3 * TILE_B + dst0, srcB_l + ko);                        \
        CP_ASYNC16(s0 + 3 * TILE_B + dst1, srcB_l + ko + rowskip);              \
    } while (0)

    ISSUE_STAGE(0, 0);
    CP_COMMIT();

    const int NIT = NFEAT / BKT;                  // 16
    for (int it = 0; it < NIT; it++) {
        int stg = it & 1;
        if (it + 1 < NIT) { ISSUE_STAGE(it + 1, stg ^ 1); CP_COMMIT(); CP_WAIT1(); }
        else              { CP_WAIT0(); }
        __syncthreads();

        uint32_t sA = sb + stg * STG_B;
        uint32_t sB = sA + 2 * TILE_B;
        #pragma unroll
        for (int ks = 0; ks < 2; ks++) {
            uint32_t kofs = ks * 32;
            uint32_t ah[2][4], al[2][4], bh[8][2], bl[8][2];
            #pragma unroll
            for (int mf = 0; mf < 2; mf++) {
                uint32_t addr = sA + (wm * 32 + mf * 16 + a_r) * (LDA * 2) + a_k + kofs;
                LDSM_X4(ah[mf][0], ah[mf][1], ah[mf][2], ah[mf][3], addr);
                LDSM_X4(al[mf][0], al[mf][1], al[mf][2], al[mf][3], addr + TILE_B);
            }
            #pragma unroll
            for (int np = 0; np < 4; np++) {
                uint32_t addr = sB + (wn * 64 + np * 16 + b_r) * (LDA * 2) + b_k + kofs;
                uint32_t t0, t1, t2, t3;
                LDSM_X4(t0, t1, t2, t3, addr);
                bh[2 * np][0] = t0; bh[2 * np][1] = t1;
                bh[2 * np + 1][0] = t2; bh[2 * np + 1][1] = t3;
                LDSM_X4(t0, t1, t2, t3, addr + TILE_B);
                bl[2 * np][0] = t0; bl[2 * np][1] = t1;
                bl[2 * np + 1][0] = t2; bl[2 * np + 1][1] = t3;
            }
            #pragma unroll
            for (int mf = 0; mf < 2; mf++)
                #pragma unroll
                for (int nf = 0; nf < 8; nf++) {
                    MMA_BF16(acc[mf][nf], ah[mf], bh[nf]);
                    MMA_BF16(acc[mf][nf], ah[mf], bl[nf]);
                    MMA_BF16(acc[mf][nf], al[mf], bh[nf]);
                }
        }
        __syncthreads();
    }

    int rr = m_blk + wm * 32 + (lane >> 2);
    int cc = n_blk + wn * 64 + 2 * (lane & 3);
    #pragma unroll
    for (int mf = 0; mf < 2; mf++)
        #pragma unroll
        for (int nf = 0; nf < 8; nf++) {
            float* d0 = g_P1 + (size_t)(rr + mf * 16) * NHID + cc + nf * 8;
            float* d1 = g_P1 + (size_t)(rr + mf * 16 + 8) * NHID + cc + nf * 8;
            *reinterpret_cast<float2*>(d0) = make_float2(acc[mf][nf][0], acc[mf][nf][1]);
            *reinterpret_cast<float2*>(d1) = make_float2(acc[mf][nf][2], acc[mf][nf][3]);
        }
}

// ---------------------------------------------------------------------------
// Kernel 4 (fused spmm_relu + gemm2): P2 = relu(norm_adj @ P1) @ W2.
// Epilogue rewritten: warp w owns classes {w, w+8, ..., w+32}; lanes stride k
// -> W2T reads are single coalesced 128B lines (fixes R7's 32x wavefront blowup).
// ---------------------------------------------------------------------------
__global__ __launch_bounds__(256) void spmm_gemm2() {
    int row = blockIdx.x;
    int t   = threadIdx.x;
    __shared__ int   snbr[CAP];
    __shared__ float sd[CAP];
    __shared__ float sh[NHID];

    int cnt = g_cnt[row];
    if (t < cnt) { int j = g_nbr[row * CAP + t]; snbr[t] = j; sd[t] = g_d[j]; }
    __syncthreads();

    float di  = g_d[row];
    float acc = di * g_P1[(size_t)row * NHID + t];
    for (int k = 0; k < cnt; k++)
        acc += sd[k] * g_P1[(size_t)snbr[k] * NHID + t];
    sh[t] = fmaxf(di * acc, 0.f);
    __syncthreads();

    int w = t >> 5, lane = t & 31;
    #pragma unroll
    for (int i = 0; i < 5; i++) {
        int c = w + 8 * i;                        // 0..39
        const float* wr = g_W2T + (size_t)c * NHID;
        float a = 0.f;
        #pragma unroll
        for (int k = lane; k < NHID; k += 32)
            a += sh[k] * wr[k];                   // coalesced 128B per iter
        #pragma unroll
        for (int o = 16; o; o >>= 1)
            a += __shfl_xor_sync(0xffffffffu, a, o);
        if (lane == 0)
            g_P2[(size_t)row * NCLASS + c] = a;
    }
}

// ---------------------------------------------------------------------------
// Kernel 5: out = log_softmax( relu( norm_adj @ P2 ) ).
// ---------------------------------------------------------------------------
__global__ __launch_bounds__(64) void spmm2_out(float* __restrict__ out) {
    int row = blockIdx.x;
    int t   = threadIdx.x;
    __shared__ int   snbr[CAP];
    __shared__ float sd[CAP];
    __shared__ float logits[NCLASS];
    __shared__ float red[2];

    int cnt = g_cnt[row];
    if (t < cnt) { int j = g_nbr[row * CAP + t]; snbr[t] = j; sd[t] = g_d[j]; }
    __syncthreads();

    float di = g_d[row];
    float v  = 0.f;
    if (t < NCLASS) {
        float acc = di * g_P2[(size_t)row * NCLASS + t];
        for (int k = 0; k < cnt; k++)
            acc += sd[k] * g_P2[(size_t)snbr[k] * NCLASS + t];
        v = fmaxf(di * acc, 0.f);
        logits[t] = v;
    }
    __syncthreads();

    if (t < 32) {
        float m = logits[t];
        if (t + 32 < NCLASS) m = fmaxf(m, logits[t + 32]);
        #pragma unroll
        for (int o = 16; o; o >>= 1) m = fmaxf(m, __shfl_xor_sync(0xffffffffu, m, o));
        if (t == 0) red[0] = m;
    }
    __syncthreads();
    float mx = red[0];
    if (t < 32) {
        float s2 = expf(logits[t] - mx);
        if (t + 32 < NCLASS) s2 += expf(logits[t + 32] - mx);
        #pragma unroll
        for (int o = 16; o; o >>= 1) s2 += __shfl_xor_sync(0xffffffffu, s2, o);
        if (t == 0) red[1] = s2;
    }
    __syncthreads();
    if (t < NCLASS)
        out[(size_t)row * NCLASS + t] = v - mx - logf(red[1]);
}

// ---------------------------------------------------------------------------
extern "C" void kernel_launch(void* const* d_in, const int* in_sizes, int n_in,
                              void* d_out, int out_size) {
    const float* x   = (const float*)d_in[0];   // [8192, 512]
    const float* adj = (const float*)d_in[1];   // [8192, 8192]
    const float* W1  = (const float*)d_in[2];   // [512, 256]
    const float* W2  = (const float*)d_in[3];   // [256, 40]
    float* out = (float*)d_out;                 // [8192, 40]

    cudaFuncSetAttribute(mma_gemm1, cudaFuncAttributeMaxDynamicSharedMemorySize, SMEM_MMA);

    build_sparse<<<N_NODES, 256>>>(adj);
    cvt_x<<<(N_NODES * NFEAT) / (4 * 256), 256>>>(x);
    cvt_w1<<<NHID, 512>>>(W1);
    cvt_w2t<<<1, 256>>>(W2);
    mma_gemm1<<<dim3(NHID / 128, N_NODES / 128), 256, SMEM_MMA>>>();
    spmm_gemm2<<<N_NODES, 256>>>();
    spmm2_out<<<N_NODES, 64>>>(out);
}

// round 9
// speedup vs baseline: 1.7686x; 1.0664x over previous
#include <cuda_runtime.h>
#include <cuda_bf16.h>
#include <math.h>
#include <cstdint>

#define N_NODES 8192
#define NFEAT   512
#define NHID    256
#define NCLASS  40
#define CAP     64

// ---------------- scratch (static device globals; no runtime allocation) ----
__device__ int   g_nbr[N_NODES * CAP];
__device__ int   g_cnt[N_NODES];
__device__ float g_d[N_NODES];
__device__ float g_P1[N_NODES * NHID];            // x @ W1 (fp32 result)
__device__ float g_P2[N_NODES * NCLASS];
__device__ float g_W2T[NCLASS * NHID];            // W2 transposed [class][k], 40 KB
__device__ __nv_bfloat16 g_xhi[N_NODES * NFEAT];  // 8 MB
__device__ __nv_bfloat16 g_xlo[N_NODES * NFEAT];  // 8 MB
__device__ __nv_bfloat16 g_w1hi[NHID * NFEAT];    // W1^T, [n][k], 256 KB
__device__ __nv_bfloat16 g_w1lo[NHID * NFEAT];

// ======================= helpers (base-target PTX only) =====================
__device__ __forceinline__ uint32_t smem_u32(const void* p) {
    uint32_t a;
    asm("{ .reg .u64 t; cvta.to.shared.u64 t, %1; cvt.u32.u64 %0, t; }" : "=r"(a) : "l"(p));
    return a;
}
#define CP_ASYNC16(dst, src) \
    asm volatile("cp.async.cg.shared.global [%0], [%1], 16;" :: "r"(dst), "l"(src))
#define CP_COMMIT()  asm volatile("cp.async.commit_group;" ::: "memory")
#define CP_WAIT1()   asm volatile("cp.async.wait_group 1;" ::: "memory")
#define CP_WAIT0()   asm volatile("cp.async.wait_group 0;" ::: "memory")
#define LDSM_X4(r0, r1, r2, r3, a) \
    asm volatile("ldmatrix.sync.aligned.m8n8.x4.shared.b16 {%0,%1,%2,%3}, [%4];" \
                 : "=r"(r0), "=r"(r1), "=r"(r2), "=r"(r3) : "r"(a))
#define MMA_BF16(d, a, b) \
    asm volatile("mma.sync.aligned.m16n8k16.row.col.f32.bf16.bf16.f32 " \
                 "{%0,%1,%2,%3}, {%4,%5,%6,%7}, {%8,%9}, {%0,%1,%2,%3};" \
                 : "+f"((d)[0]), "+f"((d)[1]), "+f"((d)[2]), "+f"((d)[3]) \
                 : "r"((a)[0]), "r"((a)[1]), "r"((a)[2]), "r"((a)[3]), \
                   "r"((b)[0]), "r"((b)[1]))

// ---------------------------------------------------------------------------
// Kernel 1: adjacency scan -> compact neighbor lists + D^{-1/2}. (unchanged)
// ---------------------------------------------------------------------------
__global__ __launch_bounds__(256) void build_sparse(const float* __restrict__ adj) {
    int row = blockIdx.x;
    int t   = threadIdx.x;
    const float4* arow = reinterpret_cast<const float4*>(adj + (size_t)row * N_NODES);

    unsigned mask = 0;
    #pragma unroll
    for (int i = 0; i < 8; i++) {
        float4 v = arow[i * 256 + t];
        if (v.x != 0.f) mask |= 1u << (i * 4 + 0);
        if (v.y != 0.f) mask |= 1u << (i * 4 + 1);
        if (v.z != 0.f) mask |= 1u << (i * 4 + 2);
        if (v.w != 0.f) mask |= 1u << (i * 4 + 3);
    }
    int c = __popc(mask);

    __shared__ int s[256];
    s[t] = c;
    __syncthreads();
    for (int off = 1; off < 256; off <<= 1) {
        int v = (t >= off) ? s[t - off] : 0;
        __syncthreads();
        s[t] += v;
        __syncthreads();
    }

    int base = row * CAP + (s[t] - c);
    unsigned m = mask;
    int k = 0;
    while (m) {
        int p = __ffs(m) - 1;
        m &= m - 1;
        int col = (((p >> 2) * 256 + t) << 2) + (p & 3);
        int slot = base + k;
        if (slot < row * CAP + CAP) g_nbr[slot] = col;
        k++;
    }
    if (t == 255) {
        int total = s[255];
        g_cnt[row] = (total > CAP) ? CAP : total;
        g_d[row]   = rsqrtf((float)(total + 1));
    }
}

// ---------------------------------------------------------------------------
// Kernel 2a: split x into bf16 hi/lo (x = hi + lo to ~16 mantissa bits).
// ---------------------------------------------------------------------------
__global__ __launch_bounds__(256) void cvt_x(const float* __restrict__ x) {
    size_t i = (size_t)blockIdx.x * 256 + threadIdx.x;
    float4 v = reinterpret_cast<const float4*>(x)[i];
    __nv_bfloat16 h0 = __float2bfloat16(v.x), h1 = __float2bfloat16(v.y);
    __nv_bfloat16 h2 = __float2bfloat16(v.z), h3 = __float2bfloat16(v.w);
    __nv_bfloat16 l0 = __float2bfloat16(v.x - __bfloat162float(h0));
    __nv_bfloat16 l1 = __float2bfloat16(v.y - __bfloat162float(h1));
    __nv_bfloat16 l2 = __float2bfloat16(v.z - __bfloat162float(h2));
    __nv_bfloat16 l3 = __float2bfloat16(v.w - __bfloat162float(h3));
    uint2 ph, pl;
    ph.x = (uint32_t)__bfloat16_as_ushort(h0) | ((uint32_t)__bfloat16_as_ushort(h1) << 16);
    ph.y = (uint32_t)__bfloat16_as_ushort(h2) | ((uint32_t)__bfloat16_as_ushort(h3) << 16);
    pl.x = (uint32_t)__bfloat16_as_ushort(l0) | ((uint32_t)__bfloat16_as_ushort(l1) << 16);
    pl.y = (uint32_t)__bfloat16_as_ushort(l2) | ((uint32_t)__bfloat16_as_ushort(l3) << 16);
    reinterpret_cast<uint2*>(g_xhi)[i] = ph;
    reinterpret_cast<uint2*>(g_xlo)[i] = pl;
}

// Kernel 2b: W1 [512,256] -> transposed K-major hi/lo [n][k].
__global__ __launch_bounds__(512) void cvt_w1(const float* __restrict__ W1) {
    int n = blockIdx.x;       // 0..255
    int k = threadIdx.x;      // 0..511
    float v = W1[(size_t)k * NHID + n];
    __nv_bfloat16 h = __float2bfloat16(v);
    __nv_bfloat16 l = __float2bfloat16(v - __bfloat162float(h));
    g_w1hi[(size_t)n * NFEAT + k] = h;
    g_w1lo[(size_t)n * NFEAT + k] = l;
}

// Kernel 2c: W2 [256,40] -> [40][256]; one class row per block (R8: grid=1
// serialized this to 12.6us; now 40-way parallel, coalesced writes).
__global__ __launch_bounds__(256) void cvt_w2t(const float* __restrict__ W2) {
    int c = blockIdx.x;       // 0..39
    int k = threadIdx.x;      // 0..255
    g_W2T[(size_t)c * NHID + k] = W2[(size_t)k * NCLASS + c];
}

// ---------------------------------------------------------------------------
// Kernel 3: g_P1 = x @ W1 via mma.sync bf16 (hi/lo compensated, fp32 accum).
// R9 retile: block tile 64x128x32 -> 256 blocks (was 128 on 148 SMs),
// smem/stage 30KB (2 stages = 60KB), warp tile 32x32, 2 blocks/SM target.
// ---------------------------------------------------------------------------
#define BKT   32
#define LDA   40                                  // bf16 stride (80 B)
#define AT_B  (64 * LDA * 2)                      // A tile: 5120 B
#define BT_B  (128 * LDA * 2)                     // B tile: 10240 B
#define STG_B (2 * AT_B + 2 * BT_B)               // Ahi|Alo|Bhi|Blo = 30720 B
#define SMEM_MMA (2 * STG_B)                      // 61440 B

__global__ __launch_bounds__(256, 2) void mma_gemm1() {
    extern __shared__ char smem[];
    uint32_t sb = smem_u32(smem);
    int tid = threadIdx.x, lane = tid & 31, wid = tid >> 5;
    int wm = wid & 1, wn = wid >> 1;              // 2(M) x 4(N) warp grid
    int bx = blockIdx.x, by = blockIdx.y;
    int m_blk = by * 64, n_blk = bx * 128;

    // A: 64 rows x 4 chunks = 256 = 1 chunk/thread. B: 128 rows x 4 = 2/thread.
    int ra = tid >> 2, ca = tid & 3;              // A chunk coords
    int rb0 = ra, rb1 = ra + 64;                  // B chunk coords (2 chunks)
    const __nv_bfloat16* srcA_h = g_xhi  + (size_t)(m_blk + ra) * NFEAT + ca * 8;
    const __nv_bfloat16* srcA_l = g_xlo  + (size_t)(m_blk + ra) * NFEAT + ca * 8;
    const __nv_bfloat16* srcB_h = g_w1hi + (size_t)(n_blk + rb0) * NFEAT + ca * 8;
    const __nv_bfloat16* srcB_l = g_w1lo + (size_t)(n_blk + rb0) * NFEAT + ca * 8;
    uint32_t dA  = ra  * (LDA * 2) + ca * 16;
    uint32_t dB0 = rb0 * (LDA * 2) + ca * 16;
    uint32_t dB1 = rb1 * (LDA * 2) + ca * 16;
    const size_t rowskip = (size_t)64 * NFEAT;    // rb0 -> rb1

    float acc[2][4][4] = {};

    uint32_t a_r = (lane & 15);
    uint32_t a_k = (lane >> 4) * 16;
    uint32_t b_r = ((lane >> 4) & 1) * 8 + (lane & 7);
    uint32_t b_k = ((lane >> 3) & 1) * 16;

    #define ISSUE_STAGE(it, stg) do {                                           \
        uint32_t s0 = sb + (stg) * STG_B;                                       \
        size_t ko = (size_t)(it) * BKT;                                         \
        CP_ASYNC16(s0 + dA,                       srcA_h + ko);                 \
        CP_ASYNC16(s0 + AT_B + dA,                srcA_l + ko);                 \
        CP_ASYNC16(s0 + 2 * AT_B + dB0,           srcB_h + ko);                 \
        CP_ASYNC16(s0 + 2 * AT_B + dB1,           srcB_h + ko + rowskip);       \
        CP_ASYNC16(s0 + 2 * AT_B + BT_B + dB0,    srcB_l + ko);                 \
        CP_ASYNC16(s0 + 2 * AT_B + BT_B + dB1,    srcB_l + ko + rowskip);       \
    } while (0)

    ISSUE_STAGE(0, 0);
    CP_COMMIT();

    const int NIT = NFEAT / BKT;                  // 16
    for (int it = 0; it < NIT; it++) {
        int stg = it & 1;
        if (it + 1 < NIT) { ISSUE_STAGE(it + 1, stg ^ 1); CP_COMMIT(); CP_WAIT1(); }
        else              { CP_WAIT0(); }
        __syncthreads();

        uint32_t sA = sb + stg * STG_B;
        uint32_t sB = sA + 2 * AT_B;
        #pragma unroll
        for (int ks = 0; ks < 2; ks++) {
            uint32_t kofs = ks * 32;
            uint32_t ah[2][4], al[2][4], bh[4][2], bl[4][2];
            #pragma unroll
            for (int mf = 0; mf < 2; mf++) {
                uint32_t addr = sA + (wm * 32 + mf * 16 + a_r) * (LDA * 2) + a_k + kofs;
                LDSM_X4(ah[mf][0], ah[mf][1], ah[mf][2], ah[mf][3], addr);
                LDSM_X4(al[mf][0], al[mf][1], al[mf][2], al[mf][3], addr + AT_B);
            }
            #pragma unroll
            for (int np = 0; np < 2; np++) {
                uint32_t addr = sB + (wn * 32 + np * 16 + b_r) * (LDA * 2) + b_k + kofs;
                uint32_t t0, t1, t2, t3;
                LDSM_X4(t0, t1, t2, t3, addr);
                bh[2 * np][0] = t0; bh[2 * np][1] = t1;
                bh[2 * np + 1][0] = t2; bh[2 * np + 1][1] = t3;
                LDSM_X4(t0, t1, t2, t3, addr + BT_B);
                bl[2 * np][0] = t0; bl[2 * np][1] = t1;
                bl[2 * np + 1][0] = t2; bl[2 * np + 1][1] = t3;
            }
            #pragma unroll
            for (int mf = 0; mf < 2; mf++)
                #pragma unroll
                for (int nf = 0; nf < 4; nf++) {
                    MMA_BF16(acc[mf][nf], ah[mf], bh[nf]);
                    MMA_BF16(acc[mf][nf], ah[mf], bl[nf]);
                    MMA_BF16(acc[mf][nf], al[mf], bh[nf]);
                }
        }
        __syncthreads();
    }

    int rr = m_blk + wm * 32 + (lane >> 2);
    int cc = n_blk + wn * 32 + 2 * (lane & 3);
    #pragma unroll
    for (int mf = 0; mf < 2; mf++)
        #pragma unroll
        for (int nf = 0; nf < 4; nf++) {
            float* d0 = g_P1 + (size_t)(rr + mf * 16) * NHID + cc + nf * 8;
            float* d1 = g_P1 + (size_t)(rr + mf * 16 + 8) * NHID + cc + nf * 8;
            *reinterpret_cast<float2*>(d0) = make_float2(acc[mf][nf][0], acc[mf][nf][1]);
            *reinterpret_cast<float2*>(d1) = make_float2(acc[mf][nf][2], acc[mf][nf][3]);
        }
}

// ---------------------------------------------------------------------------
// Kernel 4 (fused spmm_relu + gemm2): P2 = relu(norm_adj @ P1) @ W2. (R8 ver)
// ---------------------------------------------------------------------------
__global__ __launch_bounds__(256) void spmm_gemm2() {
    int row = blockIdx.x;
    int t   = threadIdx.x;
    __shared__ int   snbr[CAP];
    __shared__ float sd[CAP];
    __shared__ float sh[NHID];

    int cnt = g_cnt[row];
    if (t < cnt) { int j = g_nbr[row * CAP + t]; snbr[t] = j; sd[t] = g_d[j]; }
    __syncthreads();

    float di  = g_d[row];
    float acc = di * g_P1[(size_t)row * NHID + t];
    for (int k = 0; k < cnt; k++)
        acc += sd[k] * g_P1[(size_t)snbr[k] * NHID + t];
    sh[t] = fmaxf(di * acc, 0.f);
    __syncthreads();

    int w = t >> 5, lane = t & 31;
    #pragma unroll
    for (int i = 0; i < 5; i++) {
        int c = w + 8 * i;                        // 0..39
        const float* wr = g_W2T + (size_t)c * NHID;
        float a = 0.f;
        #pragma unroll
        for (int k = lane; k < NHID; k += 32)
            a += sh[k] * wr[k];                   // coalesced 128B per iter
        #pragma unroll
        for (int o = 16; o; o >>= 1)
            a += __shfl_xor_sync(0xffffffffu, a, o);
        if (lane == 0)
            g_P2[(size_t)row * NCLASS + c] = a;
    }
}

// ---------------------------------------------------------------------------
// Kernel 5: out = log_softmax( relu( norm_adj @ P2 ) ).
// ---------------------------------------------------------------------------
__global__ __launch_bounds__(64) void spmm2_out(float* __restrict__ out) {
    int row = blockIdx.x;
    int t   = threadIdx.x;
    __shared__ int   snbr[CAP];
    __shared__ float sd[CAP];
    __shared__ float logits[NCLASS];
    __shared__ float red[2];

    int cnt = g_cnt[row];
    if (t < cnt) { int j = g_nbr[row * CAP + t]; snbr[t] = j; sd[t] = g_d[j]; }
    __syncthreads();

    float di = g_d[row];
    float v  = 0.f;
    if (t < NCLASS) {
        float acc = di * g_P2[(size_t)row * NCLASS + t];
        for (int k = 0; k < cnt; k++)
            acc += sd[k] * g_P2[(size_t)snbr[k] * NCLASS + t];
        v = fmaxf(di * acc, 0.f);
        logits[t] = v;
    }
    __syncthreads();

    if (t < 32) {
        float m = logits[t];
        if (t + 32 < NCLASS) m = fmaxf(m, logits[t + 32]);
        #pragma unroll
        for (int o = 16; o; o >>= 1) m = fmaxf(m, __shfl_xor_sync(0xffffffffu, m, o));
        if (t == 0) red[0] = m;
    }
    __syncthreads();
    float mx = red[0];
    if (t < 32) {
        float s2 = expf(logits[t] - mx);
        if (t + 32 < NCLASS) s2 += expf(logits[t + 32] - mx);
        #pragma unroll
        for (int o = 16; o; o >>= 1) s2 += __shfl_xor_sync(0xffffffffu, s2, o);
        if (t == 0) red[1] = s2;
    }
    __syncthreads();
    if (t < NCLASS)
        out[(size_t)row * NCLASS + t] = v - mx - logf(red[1]);
}

// ---------------------------------------------------------------------------
extern "C" void kernel_launch(void* const* d_in, const int* in_sizes, int n_in,
                              void* d_out, int out_size) {
    const float* x   = (const float*)d_in[0];   // [8192, 512]
    const float* adj = (const float*)d_in[1];   // [8192, 8192]
    const float* W1  = (const float*)d_in[2];   // [512, 256]
    const float* W2  = (const float*)d_in[3];   // [256, 40]
    float* out = (float*)d_out;                 // [8192, 40]

    cudaFuncSetAttribute(mma_gemm1, cudaFuncAttributeMaxDynamicSharedMemorySize, SMEM_MMA);

    build_sparse<<<N_NODES, 256>>>(adj);
    cvt_x<<<(N_NODES * NFEAT) / (4 * 256), 256>>>(x);
    cvt_w1<<<NHID, 512>>>(W1);
    cvt_w2t<<<NCLASS, 256>>>(W2);
    mma_gemm1<<<dim3(NHID / 128, N_NODES / 64), 256, SMEM_MMA>>>();
    spmm_gemm2<<<N_NODES, 256>>>();
    spmm2_out<<<N_NODES, 64>>>(out);
}

// round 11
// speedup vs baseline: 1.8712x; 1.0580x over previous
#include <cuda_runtime.h>
#include <cuda_bf16.h>
#include <math.h>
#include <cstdint>

#define N_NODES 8192
#define NFEAT   512
#define NHID    256
#define NCLASS  40
#define CAP     64

// ---------------- scratch (static device globals; no runtime allocation) ----
__device__ int   g_nbr[N_NODES * CAP];
__device__ int   g_cnt[N_NODES];
__device__ float g_d[N_NODES];
__device__ float g_P1[N_NODES * NHID];            // x @ W1 (fp32 result)
__device__ float g_P2[N_NODES * NCLASS];
__device__ float g_W2T[NCLASS * NHID];            // W2 transposed [class][k]
__device__ __nv_bfloat16 g_xhi[N_NODES * NFEAT];  // 8 MB
__device__ __nv_bfloat16 g_xlo[N_NODES * NFEAT];  // 8 MB
__device__ __nv_bfloat16 g_w1hi[NHID * NFEAT];    // W1^T, [n][k], 256 KB
__device__ __nv_bfloat16 g_w1lo[NHID * NFEAT];

// ======================= helpers (base-target PTX only) =====================
__device__ __forceinline__ uint32_t smem_u32(const void* p) {
    uint32_t a;
    asm("{ .reg .u64 t; cvta.to.shared.u64 t, %1; cvt.u32.u64 %0, t; }" : "=r"(a) : "l"(p));
    return a;
}
#define CP_ASYNC16(dst, src) \
    asm volatile("cp.async.cg.shared.global [%0], [%1], 16;" :: "r"(dst), "l"(src))
#define CP_COMMIT()  asm volatile("cp.async.commit_group;" ::: "memory")
#define CP_WAIT1()   asm volatile("cp.async.wait_group 1;" ::: "memory")
#define CP_WAIT0()   asm volatile("cp.async.wait_group 0;" ::: "memory")
#define LDSM_X4(r0, r1, r2, r3, a) \
    asm volatile("ldmatrix.sync.aligned.m8n8.x4.shared.b16 {%0,%1,%2,%3}, [%4];" \
                 : "=r"(r0), "=r"(r1), "=r"(r2), "=r"(r3) : "r"(a))
#define MMA_BF16(d, a, b) \
    asm volatile("mma.sync.aligned.m16n8k16.row.col.f32.bf16.bf16.f32 " \
                 "{%0,%1,%2,%3}, {%4,%5,%6,%7}, {%8,%9}, {%0,%1,%2,%3};" \
                 : "+f"((d)[0]), "+f"((d)[1]), "+f"((d)[2]), "+f"((d)[3]) \
                 : "r"((a)[0]), "r"((a)[1]), "r"((a)[2]), "r"((a)[3]), \
                   "r"((b)[0]), "r"((b)[1]))

// ---------------------------------------------------------------------------
// Kernel 1 (FUSED prep): heterogeneous grid.
//   blocks [0, 8192)            : adjacency row scan -> g_nbr/g_cnt/g_d
//   blocks [8192, 12288)        : cvt_x   (x -> bf16 hi/lo)
//   blocks [12288, 12544)       : cvt_w1  (W1 -> W1^T hi/lo)
//   blocks [12544, 12584)       : cvt_w2t (W2 -> W2^T)
// All four branches independent; one launch replaces four (kills 3 launch
// floors and fills build_sparse's DRAM shadow + tail with cvt work).
// ---------------------------------------------------------------------------
#define PREP_BLOCKS (N_NODES + 4096 + 256 + 40)

__global__ __launch_bounds__(256) void prep_fused(const float* __restrict__ adj,
                                                  const float* __restrict__ x,
                                                  const float* __restrict__ W1,
                                                  const float* __restrict__ W2) {
    int b = blockIdx.x;
    int t = threadIdx.x;

    if (b < N_NODES) {
        // ---- adjacency row scan ----
        int row = b;
        const float4* arow = reinterpret_cast<const float4*>(adj + (size_t)row * N_NODES);

        unsigned mask = 0;
        #pragma unroll
        for (int i = 0; i < 8; i++) {
            float4 v = arow[i * 256 + t];
            if (v.x != 0.f) mask |= 1u << (i * 4 + 0);
            if (v.y != 0.f) mask |= 1u << (i * 4 + 1);
            if (v.z != 0.f) mask |= 1u << (i * 4 + 2);
            if (v.w != 0.f) mask |= 1u << (i * 4 + 3);
        }
        int c = __popc(mask);

        __shared__ int s[256];
        s[t] = c;
        __syncthreads();
        for (int off = 1; off < 256; off <<= 1) {
            int v = (t >= off) ? s[t - off] : 0;
            __syncthreads();
            s[t] += v;
            __syncthreads();
        }

        int base = row * CAP + (s[t] - c);
        unsigned m = mask;
        int k = 0;
        while (m) {
            int p = __ffs(m) - 1;
            m &= m - 1;
            int col = (((p >> 2) * 256 + t) << 2) + (p & 3);
            int slot = base + k;
            if (slot < row * CAP + CAP) g_nbr[slot] = col;
            k++;
        }
        if (t == 255) {
            int total = s[255];
            g_cnt[row] = (total > CAP) ? CAP : total;
            g_d[row]   = rsqrtf((float)(total + 1));
        }
    } else if (b < N_NODES + 4096) {
        // ---- cvt_x: 4096 blocks x 256 threads x 4 floats ----
        size_t i = (size_t)(b - N_NODES) * 256 + t;
        float4 v = reinterpret_cast<const float4*>(x)[i];
        __nv_bfloat16 h0 = __float2bfloat16(v.x), h1 = __float2bfloat16(v.y);
        __nv_bfloat16 h2 = __float2bfloat16(v.z), h3 = __float2bfloat16(v.w);
        __nv_bfloat16 l0 = __float2bfloat16(v.x - __bfloat162float(h0));
        __nv_bfloat16 l1 = __float2bfloat16(v.y - __bfloat162float(h1));
        __nv_bfloat16 l2 = __float2bfloat16(v.z - __bfloat162float(h2));
        __nv_bfloat16 l3 = __float2bfloat16(v.w - __bfloat162float(h3));
        uint2 ph, pl;
        ph.x = (uint32_t)__bfloat16_as_ushort(h0) | ((uint32_t)__bfloat16_as_ushort(h1) << 16);
        ph.y = (uint32_t)__bfloat16_as_ushort(h2) | ((uint32_t)__bfloat16_as_ushort(h3) << 16);
        pl.x = (uint32_t)__bfloat16_as_ushort(l0) | ((uint32_t)__bfloat16_as_ushort(l1) << 16);
        pl.y = (uint32_t)__bfloat16_as_ushort(l2) | ((uint32_t)__bfloat16_as_ushort(l3) << 16);
        reinterpret_cast<uint2*>(g_xhi)[i] = ph;
        reinterpret_cast<uint2*>(g_xlo)[i] = pl;
    } else if (b < N_NODES + 4096 + 256) {
        // ---- cvt_w1: one n-row per block; threads sweep k twice ----
        int n = b - (N_NODES + 4096);
        #pragma unroll
        for (int kk = 0; kk < 2; kk++) {
            int k = kk * 256 + t;
            float v = W1[(size_t)k * NHID + n];
            __nv_bfloat16 h = __float2bfloat16(v);
            __nv_bfloat16 l = __float2bfloat16(v - __bfloat162float(h));
            g_w1hi[(size_t)n * NFEAT + k] = h;
            g_w1lo[(size_t)n * NFEAT + k] = l;
        }
    } else {
        // ---- cvt_w2t: one class per block ----
        int c = b - (N_NODES + 4096 + 256);
        g_W2T[(size_t)c * NHID + t] = W2[(size_t)t * NCLASS + c];
    }
}

// ---------------------------------------------------------------------------
// Kernel 2: g_P1 = x @ W1 via mma.sync bf16 (hi/lo compensated, fp32 accum).
// Block tile 64x128x32, 256 blocks, warp tile 32x32, 2 blocks/SM. (R9 ver)
// ---------------------------------------------------------------------------
#define BKT   32
#define LDA   40                                  // bf16 stride (80 B)
#define AT_B  (64 * LDA * 2)                      // A tile: 5120 B
#define BT_B  (128 * LDA * 2)                     // B tile: 10240 B
#define STG_B (2 * AT_B + 2 * BT_B)               // 30720 B
#define SMEM_MMA (2 * STG_B)                      // 61440 B

__global__ __launch_bounds__(256, 2) void mma_gemm1() {
    extern __shared__ char smem[];
    uint32_t sb = smem_u32(smem);
    int tid = threadIdx.x, lane = tid & 31, wid = tid >> 5;
    int wm = wid & 1, wn = wid >> 1;              // 2(M) x 4(N) warp grid
    int bx = blockIdx.x, by = blockIdx.y;
    int m_blk = by * 64, n_blk = bx * 128;

    int ra = tid >> 2, ca = tid & 3;
    int rb0 = ra, rb1 = ra + 64;
    const __nv_bfloat16* srcA_h = g_xhi  + (size_t)(m_blk + ra) * NFEAT + ca * 8;
    const __nv_bfloat16* srcA_l = g_xlo  + (size_t)(m_blk + ra) * NFEAT + ca * 8;
    const __nv_bfloat16* srcB_h = g_w1hi + (size_t)(n_blk + rb0) * NFEAT + ca * 8;
    const __nv_bfloat16* srcB_l = g_w1lo + (size_t)(n_blk + rb0) * NFEAT + ca * 8;
    uint32_t dA  = ra  * (LDA * 2) + ca * 16;
    uint32_t dB0 = rb0 * (LDA * 2) + ca * 16;
    uint32_t dB1 = rb1 * (LDA * 2) + ca * 16;
    const size_t rowskip = (size_t)64 * NFEAT;

    float acc[2][4][4] = {};

    uint32_t a_r = (lane & 15);
    uint32_t a_k = (lane >> 4) * 16;
    uint32_t b_r = ((lane >> 4) & 1) * 8 + (lane & 7);
    uint32_t b_k = ((lane >> 3) & 1) * 16;

    #define ISSUE_STAGE(it, stg) do {                                           \
        uint32_t s0 = sb + (stg) * STG_B;                                       \
        size_t ko = (size_t)(it) * BKT;                                         \
        CP_ASYNC16(s0 + dA,                       srcA_h + ko);                 \
        CP_ASYNC16(s0 + AT_B + dA,                srcA_l + ko);                 \
        CP_ASYNC16(s0 + 2 * AT_B + dB0,           srcB_h + ko);                 \
        CP_ASYNC16(s0 + 2 * AT_B + dB1,           srcB_h + ko + rowskip);       \
        CP_ASYNC16(s0 + 2 * AT_B + BT_B + dB0,    srcB_l + ko);                 \
        CP_ASYNC16(s0 + 2 * AT_B + BT_B + dB1,    srcB_l + ko + rowskip);       \
    } while (0)

    ISSUE_STAGE(0, 0);
    CP_COMMIT();

    const int NIT = NFEAT / BKT;                  // 16
    for (int it = 0; it < NIT; it++) {
        int stg = it & 1;
        if (it + 1 < NIT) { ISSUE_STAGE(it + 1, stg ^ 1); CP_COMMIT(); CP_WAIT1(); }
        else              { CP_WAIT0(); }
        __syncthreads();

        uint32_t sA = sb + stg * STG_B;
        uint32_t sB = sA + 2 * AT_B;
        #pragma unroll
        for (int ks = 0; ks < 2; ks++) {
            uint32_t kofs = ks * 32;
            uint32_t ah[2][4], al[2][4], bh[4][2], bl[4][2];
            #pragma unroll
            for (int mf = 0; mf < 2; mf++) {
                uint32_t addr = sA + (wm * 32 + mf * 16 + a_r) * (LDA * 2) + a_k + kofs;
                LDSM_X4(ah[mf][0], ah[mf][1], ah[mf][2], ah[mf][3], addr);
                LDSM_X4(al[mf][0], al[mf][1], al[mf][2], al[mf][3], addr + AT_B);
            }
            #pragma unroll
            for (int np = 0; np < 2; np++) {
                uint32_t addr = sB + (wn * 32 + np * 16 + b_r) * (LDA * 2) + b_k + kofs;
                uint32_t t0, t1, t2, t3;
                LDSM_X4(t0, t1, t2, t3, addr);
                bh[2 * np][0] = t0; bh[2 * np][1] = t1;
                bh[2 * np + 1][0] = t2; bh[2 * np + 1][1] = t3;
                LDSM_X4(t0, t1, t2, t3, addr + BT_B);
                bl[2 * np][0] = t0; bl[2 * np][1] = t1;
                bl[2 * np + 1][0] = t2; bl[2 * np + 1][1] = t3;
            }
            #pragma unroll
            for (int mf = 0; mf < 2; mf++)
                #pragma unroll
                for (int nf = 0; nf < 4; nf++) {
                    MMA_BF16(acc[mf][nf], ah[mf], bh[nf]);
                    MMA_BF16(acc[mf][nf], ah[mf], bl[nf]);
                    MMA_BF16(acc[mf][nf], al[mf], bh[nf]);
                }
        }
        __syncthreads();
    }

    int rr = m_blk + wm * 32 + (lane >> 2);
    int cc = n_blk + wn * 32 + 2 * (lane & 3);
    #pragma unroll
    for (int mf = 0; mf < 2; mf++)
        #pragma unroll
        for (int nf = 0; nf < 4; nf++) {
            float* d0 = g_P1 + (size_t)(rr + mf * 16) * NHID + cc + nf * 8;
            float* d1 = g_P1 + (size_t)(rr + mf * 16 + 8) * NHID + cc + nf * 8;
            *reinterpret_cast<float2*>(d0) = make_float2(acc[mf][nf][0], acc[mf][nf][1]);
            *reinterpret_cast<float2*>(d1) = make_float2(acc[mf][nf][2], acc[mf][nf][3]);
        }
}

// ---------------------------------------------------------------------------
// Kernel 3 (fused spmm_relu + gemm2): P2 = relu(norm_adj @ P1) @ W2.
// ---------------------------------------------------------------------------
__global__ __launch_bounds__(256) void spmm_gemm2() {
    int row = blockIdx.x;
    int t   = threadIdx.x;
    __shared__ int   snbr[CAP];
    __shared__ float sd[CAP];
    __shared__ float sh[NHID];

    int cnt = g_cnt[row];
    if (t < cnt) { int j = g_nbr[row * CAP + t]; snbr[t] = j; sd[t] = g_d[j]; }
    __syncthreads();

    float di  = g_d[row];
    float acc = di * g_P1[(size_t)row * NHID + t];
    for (int k = 0; k < cnt; k++)
        acc += sd[k] * g_P1[(size_t)snbr[k] * NHID + t];
    sh[t] = fmaxf(di * acc, 0.f);
    __syncthreads();

    int w = t >> 5, lane = t & 31;
    #pragma unroll
    for (int i = 0; i < 5; i++) {
        int c = w + 8 * i;                        // 0..39
        const float* wr = g_W2T + (size_t)c * NHID;
        float a = 0.f;
        #pragma unroll
        for (int k = lane; k < NHID; k += 32)
            a += sh[k] * wr[k];
        #pragma unroll
        for (int o = 16; o; o >>= 1)
            a += __shfl_xor_sync(0xffffffffu, a, o);
        if (lane == 0)
            g_P2[(size_t)row * NCLASS + c] = a;
    }
}

// ---------------------------------------------------------------------------
// Kernel 4: out = log_softmax( relu( norm_adj @ P2 ) ). Dual-accumulator
// cnt-loop (even/odd) to break the single FMA dependency chain.
// ---------------------------------------------------------------------------
__global__ __launch_bounds__(64) void spmm2_out(float* __restrict__ out) {
    int row = blockIdx.x;
    int t   = threadIdx.x;
    __shared__ int   snbr[CAP];
    __shared__ float sd[CAP];
    __shared__ float logits[NCLASS];
    __shared__ float red[2];

    int cnt = g_cnt[row];
    if (t < cnt) { int j = g_nbr[row * CAP + t]; snbr[t] = j; sd[t] = g_d[j]; }
    __syncthreads();

    float di = g_d[row];
    float v  = 0.f;
    if (t < NCLASS) {
        float acc0 = di * g_P2[(size_t)row * NCLASS + t];
        float acc1 = 0.f;
        int k = 0;
        for (; k + 1 < cnt; k += 2) {
            acc0 += sd[k]     * g_P2[(size_t)snbr[k]     * NCLASS + t];
            acc1 += sd[k + 1] * g_P2[(size_t)snbr[k + 1] * NCLASS + t];
        }
        if (k < cnt) acc0 += sd[k] * g_P2[(size_t)snbr[k] * NCLASS + t];
        v = fmaxf(di * (acc0 + acc1), 0.f);
        logits[t] = v;
    }
    __syncthreads();

    if (t < 32) {
        float m = logits[t];
        if (t + 32 < NCLASS) m = fmaxf(m, logits[t + 32]);
        #pragma unroll
        for (int o = 16; o; o >>= 1) m = fmaxf(m, __shfl_xor_sync(0xffffffffu, m, o));
        if (t == 0) red[0] = m;
    }
    __syncthreads();
    float mx = red[0];
    if (t < 32) {
        float s2 = expf(logits[t] - mx);
        if (t + 32 < NCLASS) s2 += expf(logits[t + 32] - mx);
        #pragma unroll
        for (int o = 16; o; o >>= 1) s2 += __shfl_xor_sync(0xffffffffu, s2, o);
        if (t == 0) red[1] = s2;
    }
    __syncthreads();
    if (t < NCLASS)
        out[(size_t)row * NCLASS + t] = v - mx - logf(red[1]);
}

// ---------------------------------------------------------------------------
extern "C" void kernel_launch(void* const* d_in, const int* in_sizes, int n_in,
                              void* d_out, int out_size) {
    const float* x   = (const float*)d_in[0];   // [8192, 512]
    const float* adj = (const float*)d_in[1];   // [8192, 8192]
    const float* W1  = (const float*)d_in[2];   // [512, 256]
    const float* W2  = (const float*)d_in[3];   // [256, 40]
    float* out = (float*)d_out;                 // [8192, 40]

    cudaFuncSetAttribute(mma_gemm1, cudaFuncAttributeMaxDynamicSharedMemorySize, SMEM_MMA);

    prep_fused<<<PREP_BLOCKS, 256>>>(adj, x, W1, W2);
    mma_gemm1<<<dim3(NHID / 128, N_NODES / 64), 256, SMEM_MMA>>>();
    spmm_gemm2<<<N_NODES, 256>>>();
    spmm2_out<<<N_NODES, 64>>>(out);
}

// round 12
// speedup vs baseline: 1.8862x; 1.0080x over previous
#include <cuda_runtime.h>
#include <cuda_bf16.h>
#include <math.h>
#include <cstdint>

#define N_NODES 8192
#define NFEAT   512
#define NHID    256
#define NCLASS  40
#define CAP     64

// ---------------- scratch (static device globals; no runtime allocation) ----
__device__ int   g_nbr[N_NODES * CAP];
__device__ int   g_cnt[N_NODES];
__device__ float g_d[N_NODES];
__device__ float g_P1[N_NODES * NHID];            // x @ W1 (fp32 result)
__device__ float g_P2[N_NODES * NCLASS];
__device__ float g_W2T[NCLASS * NHID];            // W2 transposed [class][k]
__device__ __nv_bfloat16 g_xhi[N_NODES * NFEAT];  // 8 MB
__device__ __nv_bfloat16 g_xlo[N_NODES * NFEAT];  // 8 MB
__device__ __nv_bfloat16 g_w1hi[NHID * NFEAT];    // W1^T, [n][k], 256 KB
__device__ __nv_bfloat16 g_w1lo[NHID * NFEAT];

// ======================= helpers (base-target PTX only) =====================
__device__ __forceinline__ uint32_t smem_u32(const void* p) {
    uint32_t a;
    asm("{ .reg .u64 t; cvta.to.shared.u64 t, %1; cvt.u32.u64 %0, t; }" : "=r"(a) : "l"(p));
    return a;
}
#define CP_ASYNC16(dst, src) \
    asm volatile("cp.async.cg.shared.global [%0], [%1], 16;" :: "r"(dst), "l"(src))
#define CP_COMMIT()  asm volatile("cp.async.commit_group;" ::: "memory")
#define CP_WAIT1()   asm volatile("cp.async.wait_group 1;" ::: "memory")
#define CP_WAIT0()   asm volatile("cp.async.wait_group 0;" ::: "memory")
#define LDSM_X4(r0, r1, r2, r3, a) \
    asm volatile("ldmatrix.sync.aligned.m8n8.x4.shared.b16 {%0,%1,%2,%3}, [%4];" \
                 : "=r"(r0), "=r"(r1), "=r"(r2), "=r"(r3) : "r"(a))
#define MMA_BF16(d, a, b) \
    asm volatile("mma.sync.aligned.m16n8k16.row.col.f32.bf16.bf16.f32 " \
                 "{%0,%1,%2,%3}, {%4,%5,%6,%7}, {%8,%9}, {%0,%1,%2,%3};" \
                 : "+f"((d)[0]), "+f"((d)[1]), "+f"((d)[2]), "+f"((d)[3]) \
                 : "r"((a)[0]), "r"((a)[1]), "r"((a)[2]), "r"((a)[3]), \
                   "r"((b)[0]), "r"((b)[1]))

// ---------------------------------------------------------------------------
// Kernel 1 (FUSED prep): heterogeneous grid. (unchanged from R11)
//   blocks [0, 8192)            : adjacency row scan -> g_nbr/g_cnt/g_d
//   blocks [8192, 12288)        : cvt_x   (x -> bf16 hi/lo)
//   blocks [12288, 12544)       : cvt_w1  (W1 -> W1^T hi/lo)
//   blocks [12544, 12584)       : cvt_w2t (W2 -> W2^T)
// ---------------------------------------------------------------------------
#define PREP_BLOCKS (N_NODES + 4096 + 256 + 40)

__global__ __launch_bounds__(256) void prep_fused(const float* __restrict__ adj,
                                                  const float* __restrict__ x,
                                                  const float* __restrict__ W1,
                                                  const float* __restrict__ W2) {
    int b = blockIdx.x;
    int t = threadIdx.x;

    if (b < N_NODES) {
        int row = b;
        const float4* arow = reinterpret_cast<const float4*>(adj + (size_t)row * N_NODES);

        unsigned mask = 0;
        #pragma unroll
        for (int i = 0; i < 8; i++) {
            float4 v = arow[i * 256 + t];
            if (v.x != 0.f) mask |= 1u << (i * 4 + 0);
            if (v.y != 0.f) mask |= 1u << (i * 4 + 1);
            if (v.z != 0.f) mask |= 1u << (i * 4 + 2);
            if (v.w != 0.f) mask |= 1u << (i * 4 + 3);
        }
        int c = __popc(mask);

        __shared__ int s[256];
        s[t] = c;
        __syncthreads();
        for (int off = 1; off < 256; off <<= 1) {
            int v = (t >= off) ? s[t - off] : 0;
            __syncthreads();
            s[t] += v;
            __syncthreads();
        }

        int base = row * CAP + (s[t] - c);
        unsigned m = mask;
        int k = 0;
        while (m) {
            int p = __ffs(m) - 1;
            m &= m - 1;
            int col = (((p >> 2) * 256 + t) << 2) + (p & 3);
            int slot = base + k;
            if (slot < row * CAP + CAP) g_nbr[slot] = col;
            k++;
        }
        if (t == 255) {
            int total = s[255];
            g_cnt[row] = (total > CAP) ? CAP : total;
            g_d[row]   = rsqrtf((float)(total + 1));
        }
    } else if (b < N_NODES + 4096) {
        size_t i = (size_t)(b - N_NODES) * 256 + t;
        float4 v = reinterpret_cast<const float4*>(x)[i];
        __nv_bfloat16 h0 = __float2bfloat16(v.x), h1 = __float2bfloat16(v.y);
        __nv_bfloat16 h2 = __float2bfloat16(v.z), h3 = __float2bfloat16(v.w);
        __nv_bfloat16 l0 = __float2bfloat16(v.x - __bfloat162float(h0));
        __nv_bfloat16 l1 = __float2bfloat16(v.y - __bfloat162float(h1));
        __nv_bfloat16 l2 = __float2bfloat16(v.z - __bfloat162float(h2));
        __nv_bfloat16 l3 = __float2bfloat16(v.w - __bfloat162float(h3));
        uint2 ph, pl;
        ph.x = (uint32_t)__bfloat16_as_ushort(h0) | ((uint32_t)__bfloat16_as_ushort(h1) << 16);
        ph.y = (uint32_t)__bfloat16_as_ushort(h2) | ((uint32_t)__bfloat16_as_ushort(h3) << 16);
        pl.x = (uint32_t)__bfloat16_as_ushort(l0) | ((uint32_t)__bfloat16_as_ushort(l1) << 16);
        pl.y = (uint32_t)__bfloat16_as_ushort(l2) | ((uint32_t)__bfloat16_as_ushort(l3) << 16);
        reinterpret_cast<uint2*>(g_xhi)[i] = ph;
        reinterpret_cast<uint2*>(g_xlo)[i] = pl;
    } else if (b < N_NODES + 4096 + 256) {
        int n = b - (N_NODES + 4096);
        #pragma unroll
        for (int kk = 0; kk < 2; kk++) {
            int k = kk * 256 + t;
            float v = W1[(size_t)k * NHID + n];
            __nv_bfloat16 h = __float2bfloat16(v);
            __nv_bfloat16 l = __float2bfloat16(v - __bfloat162float(h));
            g_w1hi[(size_t)n * NFEAT + k] = h;
            g_w1lo[(size_t)n * NFEAT + k] = l;
        }
    } else {
        int c = b - (N_NODES + 4096 + 256);
        g_W2T[(size_t)c * NHID + t] = W2[(size_t)t * NCLASS + c];
    }
}

// ---------------------------------------------------------------------------
// Kernel 2: g_P1 = x @ W1 via mma.sync bf16. (unchanged from R9/R11)
// ---------------------------------------------------------------------------
#define BKT   32
#define LDA   40                                  // bf16 stride (80 B)
#define AT_B  (64 * LDA * 2)                      // A tile: 5120 B
#define BT_B  (128 * LDA * 2)                     // B tile: 10240 B
#define STG_B (2 * AT_B + 2 * BT_B)               // 30720 B
#define SMEM_MMA (2 * STG_B)                      // 61440 B

__global__ __launch_bounds__(256, 2) void mma_gemm1() {
    extern __shared__ char smem[];
    uint32_t sb = smem_u32(smem);
    int tid = threadIdx.x, lane = tid & 31, wid = tid >> 5;
    int wm = wid & 1, wn = wid >> 1;              // 2(M) x 4(N) warp grid
    int bx = blockIdx.x, by = blockIdx.y;
    int m_blk = by * 64, n_blk = bx * 128;

    int ra = tid >> 2, ca = tid & 3;
    int rb0 = ra, rb1 = ra + 64;
    const __nv_bfloat16* srcA_h = g_xhi  + (size_t)(m_blk + ra) * NFEAT + ca * 8;
    const __nv_bfloat16* srcA_l = g_xlo  + (size_t)(m_blk + ra) * NFEAT + ca * 8;
    const __nv_bfloat16* srcB_h = g_w1hi + (size_t)(n_blk + rb0) * NFEAT + ca * 8;
    const __nv_bfloat16* srcB_l = g_w1lo + (size_t)(n_blk + rb0) * NFEAT + ca * 8;
    uint32_t dA  = ra  * (LDA * 2) + ca * 16;
    uint32_t dB0 = rb0 * (LDA * 2) + ca * 16;
    uint32_t dB1 = rb1 * (LDA * 2) + ca * 16;
    const size_t rowskip = (size_t)64 * NFEAT;

    float acc[2][4][4] = {};

    uint32_t a_r = (lane & 15);
    uint32_t a_k = (lane >> 4) * 16;
    uint32_t b_r = ((lane >> 4) & 1) * 8 + (lane & 7);
    uint32_t b_k = ((lane >> 3) & 1) * 16;

    #define ISSUE_STAGE(it, stg) do {                                           \
        uint32_t s0 = sb + (stg) * STG_B;                                       \
        size_t ko = (size_t)(it) * BKT;                                         \
        CP_ASYNC16(s0 + dA,                       srcA_h + ko);                 \
        CP_ASYNC16(s0 + AT_B + dA,                srcA_l + ko);                 \
        CP_ASYNC16(s0 + 2 * AT_B + dB0,           srcB_h + ko);                 \
        CP_ASYNC16(s0 + 2 * AT_B + dB1,           srcB_h + ko + rowskip);       \
        CP_ASYNC16(s0 + 2 * AT_B + BT_B + dB0,    srcB_l + ko);                 \
        CP_ASYNC16(s0 + 2 * AT_B + BT_B + dB1,    srcB_l + ko + rowskip);       \
    } while (0)

    ISSUE_STAGE(0, 0);
    CP_COMMIT();

    const int NIT = NFEAT / BKT;                  // 16
    for (int it = 0; it < NIT; it++) {
        int stg = it & 1;
        if (it + 1 < NIT) { ISSUE_STAGE(it + 1, stg ^ 1); CP_COMMIT(); CP_WAIT1(); }
        else              { CP_WAIT0(); }
        __syncthreads();

        uint32_t sA = sb + stg * STG_B;
        uint32_t sB = sA + 2 * AT_B;
        #pragma unroll
        for (int ks = 0; ks < 2; ks++) {
            uint32_t kofs = ks * 32;
            uint32_t ah[2][4], al[2][4], bh[4][2], bl[4][2];
            #pragma unroll
            for (int mf = 0; mf < 2; mf++) {
                uint32_t addr = sA + (wm * 32 + mf * 16 + a_r) * (LDA * 2) + a_k + kofs;
                LDSM_X4(ah[mf][0], ah[mf][1], ah[mf][2], ah[mf][3], addr);
                LDSM_X4(al[mf][0], al[mf][1], al[mf][2], al[mf][3], addr + AT_B);
            }
            #pragma unroll
            for (int np = 0; np < 2; np++) {
                uint32_t addr = sB + (wn * 32 + np * 16 + b_r) * (LDA * 2) + b_k + kofs;
                uint32_t t0, t1, t2, t3;
                LDSM_X4(t0, t1, t2, t3, addr);
                bh[2 * np][0] = t0; bh[2 * np][1] = t1;
                bh[2 * np + 1][0] = t2; bh[2 * np + 1][1] = t3;
                LDSM_X4(t0, t1, t2, t3, addr + BT_B);
                bl[2 * np][0] = t0; bl[2 * np][1] = t1;
                bl[2 * np + 1][0] = t2; bl[2 * np + 1][1] = t3;
            }
            #pragma unroll
            for (int mf = 0; mf < 2; mf++)
                #pragma unroll
                for (int nf = 0; nf < 4; nf++) {
                    MMA_BF16(acc[mf][nf], ah[mf], bh[nf]);
                    MMA_BF16(acc[mf][nf], ah[mf], bl[nf]);
                    MMA_BF16(acc[mf][nf], al[mf], bh[nf]);
                }
        }
        __syncthreads();
    }

    int rr = m_blk + wm * 32 + (lane >> 2);
    int cc = n_blk + wn * 32 + 2 * (lane & 3);
    #pragma unroll
    for (int mf = 0; mf < 2; mf++)
        #pragma unroll
        for (int nf = 0; nf < 4; nf++) {
            float* d0 = g_P1 + (size_t)(rr + mf * 16) * NHID + cc + nf * 8;
            float* d1 = g_P1 + (size_t)(rr + mf * 16 + 8) * NHID + cc + nf * 8;
            *reinterpret_cast<float2*>(d0) = make_float2(acc[mf][nf][0], acc[mf][nf][1]);
            *reinterpret_cast<float2*>(d1) = make_float2(acc[mf][nf][2], acc[mf][nf][3]);
        }
}

// ---------------------------------------------------------------------------
// Kernel 3 (fused spmm_relu + gemm2): P2 = relu(norm_adj @ P1) @ W2. (unchanged)
// ---------------------------------------------------------------------------
__global__ __launch_bounds__(256) void spmm_gemm2() {
    int row = blockIdx.x;
    int t   = threadIdx.x;
    __shared__ int   snbr[CAP];
    __shared__ float sd[CAP];
    __shared__ float sh[NHID];

    int cnt = g_cnt[row];
    if (t < cnt) { int j = g_nbr[row * CAP + t]; snbr[t] = j; sd[t] = g_d[j]; }
    __syncthreads();

    float di  = g_d[row];
    float acc = di * g_P1[(size_t)row * NHID + t];
    for (int k = 0; k < cnt; k++)
        acc += sd[k] * g_P1[(size_t)snbr[k] * NHID + t];
    sh[t] = fmaxf(di * acc, 0.f);
    __syncthreads();

    int w = t >> 5, lane = t & 31;
    #pragma unroll
    for (int i = 0; i < 5; i++) {
        int c = w + 8 * i;                        // 0..39
        const float* wr = g_W2T + (size_t)c * NHID;
        float a = 0.f;
        #pragma unroll
        for (int k = lane; k < NHID; k += 32)
            a += sh[k] * wr[k];
        #pragma unroll
        for (int o = 16; o; o >>= 1)
            a += __shfl_xor_sync(0xffffffffu, a, o);
        if (lane == 0)
            g_P2[(size_t)row * NCLASS + c] = a;
    }
}

// ---------------------------------------------------------------------------
// Kernel 4 (REWRITTEN): out = log_softmax( relu( norm_adj @ P2 ) ).
// One WARP per row (8 rows / 256-thread block, grid 1024). Lane l owns class
// l, and class 32+l for l<8. Neighbor idx/degree via uniform broadcast LDG.
// log-softmax entirely in shfl — no shared memory, no block barriers.
// ---------------------------------------------------------------------------
__global__ __launch_bounds__(256) void spmm2_out(float* __restrict__ out) {
    int warp = threadIdx.x >> 5;
    int lane = threadIdx.x & 31;
    int row  = blockIdx.x * 8 + warp;

    int   cnt = g_cnt[row];
    float di  = g_d[row];

    const float* p2r = g_P2 + (size_t)row * NCLASS;
    bool hi = (lane < NCLASS - 32);               // lane < 8
    float a0 = di * p2r[lane];
    float a1 = hi ? di * p2r[32 + lane] : 0.f;
    float b0 = 0.f, b1 = 0.f;

    const int* nrow = g_nbr + row * CAP;
    int k = 0;
    for (; k + 1 < cnt; k += 2) {
        int   j0 = nrow[k],     j1 = nrow[k + 1];      // uniform broadcast
        float w0 = g_d[j0],     w1 = g_d[j1];
        const float* q0 = g_P2 + (size_t)j0 * NCLASS;
        const float* q1 = g_P2 + (size_t)j1 * NCLASS;
        a0 += w0 * q0[lane];
        b0 += w1 * q1[lane];
        if (hi) { a1 += w0 * q0[32 + lane]; b1 += w1 * q1[32 + lane]; }
    }
    if (k < cnt) {
        int   j0 = nrow[k];
        float w0 = g_d[j0];
        const float* q0 = g_P2 + (size_t)j0 * NCLASS;
        a0 += w0 * q0[lane];
        if (hi) a1 += w0 * q0[32 + lane];
    }

    float v0 = fmaxf(di * (a0 + b0), 0.f);                       // class lane
    float v1 = hi ? fmaxf(di * (a1 + b1), 0.f) : -1e30f;         // class 32+lane

    // warp-reduce max over 40 values
    float m = fmaxf(v0, v1);
    #pragma unroll
    for (int o = 16; o; o >>= 1) m = fmaxf(m, __shfl_xor_sync(0xffffffffu, m, o));

    // warp-reduce sum of exp
    float s = expf(v0 - m) + (hi ? expf(v1 - m) : 0.f);
    #pragma unroll
    for (int o = 16; o; o >>= 1) s += __shfl_xor_sync(0xffffffffu, s, o);

    float ls = m + logf(s);
    float* orow = out + (size_t)row * NCLASS;
    orow[lane] = v0 - ls;
    if (hi) orow[32 + lane] = v1 - ls;
}

// ---------------------------------------------------------------------------
extern "C" void kernel_launch(void* const* d_in, const int* in_sizes, int n_in,
                              void* d_out, int out_size) {
    const float* x   = (const float*)d_in[0];   // [8192, 512]
    const float* adj = (const float*)d_in[1];   // [8192, 8192]
    const float* W1  = (const float*)d_in[2];   // [512, 256]
    const float* W2  = (const float*)d_in[3];   // [256, 40]
    float* out = (float*)d_out;                 // [8192, 40]

    cudaFuncSetAttribute(mma_gemm1, cudaFuncAttributeMaxDynamicSharedMemorySize, SMEM_MMA);

    prep_fused<<<PREP_BLOCKS, 256>>>(adj, x, W1, W2);
    mma_gemm1<<<dim3(NHID / 128, N_NODES / 64), 256, SMEM_MMA>>>();
    spmm_gemm2<<<N_NODES, 256>>>();
    spmm2_out<<<N_NODES / 8, 256>>>(out);
}

// round 17
// speedup vs baseline: 1.8985x; 1.0065x over previous
#include <cuda_runtime.h>
#include <cuda_bf16.h>
#include <math.h>
#include <cstdint>

#define N_NODES 8192
#define NFEAT   512
#define NHID    256
#define NCLASS  40
#define CAP     64
#define P2LD    64        // padded P2 row stride (floats): 256B-aligned rows

// ---------------- scratch (static device globals; no runtime allocation) ----
__device__ int   g_nbr[N_NODES * CAP];
__device__ int   g_cnt[N_NODES];
__device__ float g_d[N_NODES];
__device__ float g_P1[N_NODES * NHID];            // x @ W1 (fp32 result)
__device__ float g_P2[N_NODES * P2LD];            // padded: [row][64]
__device__ float g_W2T[NCLASS * NHID];            // W2 transposed [class][k]
__device__ __nv_bfloat16 g_xhi[N_NODES * NFEAT];  // 8 MB
__device__ __nv_bfloat16 g_xlo[N_NODES * NFEAT];  // 8 MB
__device__ __nv_bfloat16 g_w1hi[NHID * NFEAT];    // W1^T, [n][k], 256 KB
__device__ __nv_bfloat16 g_w1lo[NHID * NFEAT];

// ======================= helpers (base-target PTX only) =====================
__device__ __forceinline__ uint32_t smem_u32(const void* p) {
    uint32_t a;
    asm("{ .reg .u64 t; cvta.to.shared.u64 t, %1; cvt.u32.u64 %0, t; }" : "=r"(a) : "l"(p));
    return a;
}
#define CP_ASYNC16(dst, src) \
    asm volatile("cp.async.cg.shared.global [%0], [%1], 16;" :: "r"(dst), "l"(src))
#define CP_COMMIT()  asm volatile("cp.async.commit_group;" ::: "memory")
#define CP_WAIT1()   asm volatile("cp.async.wait_group 1;" ::: "memory")
#define CP_WAIT0()   asm volatile("cp.async.wait_group 0;" ::: "memory")
#define LDSM_X4(r0, r1, r2, r3, a) \
    asm volatile("ldmatrix.sync.aligned.m8n8.x4.shared.b16 {%0,%1,%2,%3}, [%4];" \
                 : "=r"(r0), "=r"(r1), "=r"(r2), "=r"(r3) : "r"(a))
#define MMA_BF16(d, a, b) \
    asm volatile("mma.sync.aligned.m16n8k16.row.col.f32.bf16.bf16.f32 " \
                 "{%0,%1,%2,%3}, {%4,%5,%6,%7}, {%8,%9}, {%0,%1,%2,%3};" \
                 : "+f"((d)[0]), "+f"((d)[1]), "+f"((d)[2]), "+f"((d)[3]) \
                 : "r"((a)[0]), "r"((a)[1]), "r"((a)[2]), "r"((a)[3]), \
                   "r"((b)[0]), "r"((b)[1]))

// ---------------------------------------------------------------------------
// Kernel 1 (FUSED prep): heterogeneous grid. (unchanged from R11)
// ---------------------------------------------------------------------------
#define PREP_BLOCKS (N_NODES + 4096 + 256 + 40)

__global__ __launch_bounds__(256) void prep_fused(const float* __restrict__ adj,
                                                  const float* __restrict__ x,
                                                  const float* __restrict__ W1,
                                                  const float* __restrict__ W2) {
    int b = blockIdx.x;
    int t = threadIdx.x;

    if (b < N_NODES) {
        int row = b;
        const float4* arow = reinterpret_cast<const float4*>(adj + (size_t)row * N_NODES);

        unsigned mask = 0;
        #pragma unroll
        for (int i = 0; i < 8; i++) {
            float4 v = arow[i * 256 + t];
            if (v.x != 0.f) mask |= 1u << (i * 4 + 0);
            if (v.y != 0.f) mask |= 1u << (i * 4 + 1);
            if (v.z != 0.f) mask |= 1u << (i * 4 + 2);
            if (v.w != 0.f) mask |= 1u << (i * 4 + 3);
        }
        int c = __popc(mask);

        __shared__ int s[256];
        s[t] = c;
        __syncthreads();
        for (int off = 1; off < 256; off <<= 1) {
            int v = (t >= off) ? s[t - off] : 0;
            __syncthreads();
            s[t] += v;
            __syncthreads();
        }

        int base = row * CAP + (s[t] - c);
        unsigned m = mask;
        int k = 0;
        while (m) {
            int p = __ffs(m) - 1;
            m &= m - 1;
            int col = (((p >> 2) * 256 + t) << 2) + (p & 3);
            int slot = base + k;
            if (slot < row * CAP + CAP) g_nbr[slot] = col;
            k++;
        }
        if (t == 255) {
            int total = s[255];
            g_cnt[row] = (total > CAP) ? CAP : total;
            g_d[row]   = rsqrtf((float)(total + 1));
        }
    } else if (b < N_NODES + 4096) {
        size_t i = (size_t)(b - N_NODES) * 256 + t;
        float4 v = reinterpret_cast<const float4*>(x)[i];
        __nv_bfloat16 h0 = __float2bfloat16(v.x), h1 = __float2bfloat16(v.y);
        __nv_bfloat16 h2 = __float2bfloat16(v.z), h3 = __float2bfloat16(v.w);
        __nv_bfloat16 l0 = __float2bfloat16(v.x - __bfloat162float(h0));
        __nv_bfloat16 l1 = __float2bfloat16(v.y - __bfloat162float(h1));
        __nv_bfloat16 l2 = __float2bfloat16(v.z - __bfloat162float(h2));
        __nv_bfloat16 l3 = __float2bfloat16(v.w - __bfloat162float(h3));
        uint2 ph, pl;
        ph.x = (uint32_t)__bfloat16_as_ushort(h0) | ((uint32_t)__bfloat16_as_ushort(h1) << 16);
        ph.y = (uint32_t)__bfloat16_as_ushort(h2) | ((uint32_t)__bfloat16_as_ushort(h3) << 16);
        pl.x = (uint32_t)__bfloat16_as_ushort(l0) | ((uint32_t)__bfloat16_as_ushort(l1) << 16);
        pl.y = (uint32_t)__bfloat16_as_ushort(l2) | ((uint32_t)__bfloat16_as_ushort(l3) << 16);
        reinterpret_cast<uint2*>(g_xhi)[i] = ph;
        reinterpret_cast<uint2*>(g_xlo)[i] = pl;
    } else if (b < N_NODES + 4096 + 256) {
        int n = b - (N_NODES + 4096);
        #pragma unroll
        for (int kk = 0; kk < 2; kk++) {
            int k = kk * 256 + t;
            float v = W1[(size_t)k * NHID + n];
            __nv_bfloat16 h = __float2bfloat16(v);
            __nv_bfloat16 l = __float2bfloat16(v - __bfloat162float(h));
            g_w1hi[(size_t)n * NFEAT + k] = h;
            g_w1lo[(size_t)n * NFEAT + k] = l;
        }
    } else {
        int c = b - (N_NODES + 4096 + 256);
        g_W2T[(size_t)c * NHID + t] = W2[(size_t)t * NCLASS + c];
    }
}

// ---------------------------------------------------------------------------
// Kernel 2: g_P1 = x @ W1 via mma.sync bf16. (unchanged from R9/R11)
// ---------------------------------------------------------------------------
#define BKT   32
#define LDA   40                                  // bf16 stride (80 B)
#define AT_B  (64 * LDA * 2)                      // A tile: 5120 B
#define BT_B  (128 * LDA * 2)                     // B tile: 10240 B
#define STG_B (2 * AT_B + 2 * BT_B)               // 30720 B
#define SMEM_MMA (2 * STG_B)                      // 61440 B

__global__ __launch_bounds__(256, 2) void mma_gemm1() {
    extern __shared__ char smem[];
    uint32_t sb = smem_u32(smem);
    int tid = threadIdx.x, lane = tid & 31, wid = tid >> 5;
    int wm = wid & 1, wn = wid >> 1;              // 2(M) x 4(N) warp grid
    int bx = blockIdx.x, by = blockIdx.y;
    int m_blk = by * 64, n_blk = bx * 128;

    int ra = tid >> 2, ca = tid & 3;
    int rb0 = ra, rb1 = ra + 64;
    const __nv_bfloat16* srcA_h = g_xhi  + (size_t)(m_blk + ra) * NFEAT + ca * 8;
    const __nv_bfloat16* srcA_l = g_xlo  + (size_t)(m_blk + ra) * NFEAT + ca * 8;
    const __nv_bfloat16* srcB_h = g_w1hi + (size_t)(n_blk + rb0) * NFEAT + ca * 8;
    const __nv_bfloat16* srcB_l = g_w1lo + (size_t)(n_blk + rb0) * NFEAT + ca * 8;
    uint32_t dA  = ra  * (LDA * 2) + ca * 16;
    uint32_t dB0 = rb0 * (LDA * 2) + ca * 16;
    uint32_t dB1 = rb1 * (LDA * 2) + ca * 16;
    const size_t rowskip = (size_t)64 * NFEAT;

    float acc[2][4][4] = {};

    uint32_t a_r = (lane & 15);
    uint32_t a_k = (lane >> 4) * 16;
    uint32_t b_r = ((lane >> 4) & 1) * 8 + (lane & 7);
    uint32_t b_k = ((lane >> 3) & 1) * 16;

    #define ISSUE_STAGE(it, stg) do {                                           \
        uint32_t s0 = sb + (stg) * STG_B;                                       \
        size_t ko = (size_t)(it) * BKT;                                         \
        CP_ASYNC16(s0 + dA,                       srcA_h + ko);                 \
        CP_ASYNC16(s0 + AT_B + dA,                srcA_l + ko);                 \
        CP_ASYNC16(s0 + 2 * AT_B + dB0,           srcB_h + ko);                 \
        CP_ASYNC16(s0 + 2 * AT_B + dB1,           srcB_h + ko + rowskip);       \
        CP_ASYNC16(s0 + 2 * AT_B + BT_B + dB0,    srcB_l + ko);                 \
        CP_ASYNC16(s0 + 2 * AT_B + BT_B + dB1,    srcB_l + ko + rowskip);       \
    } while (0)

    ISSUE_STAGE(0, 0);
    CP_COMMIT();

    const int NIT = NFEAT / BKT;                  // 16
    for (int it = 0; it < NIT; it++) {
        int stg = it & 1;
        if (it + 1 < NIT) { ISSUE_STAGE(it + 1, stg ^ 1); CP_COMMIT(); CP_WAIT1(); }
        else              { CP_WAIT0(); }
        __syncthreads();

        uint32_t sA = sb + stg * STG_B;
        uint32_t sB = sA + 2 * AT_B;
        #pragma unroll
        for (int ks = 0; ks < 2; ks++) {
            uint32_t kofs = ks * 32;
            uint32_t ah[2][4], al[2][4], bh[4][2], bl[4][2];
            #pragma unroll
            for (int mf = 0; mf < 2; mf++) {
                uint32_t addr = sA + (wm * 32 + mf * 16 + a_r) * (LDA * 2) + a_k + kofs;
                LDSM_X4(ah[mf][0], ah[mf][1], ah[mf][2], ah[mf][3], addr);
                LDSM_X4(al[mf][0], al[mf][1], al[mf][2], al[mf][3], addr + AT_B);
            }
            #pragma unroll
            for (int np = 0; np < 2; np++) {
                uint32_t addr = sB + (wn * 32 + np * 16 + b_r) * (LDA * 2) + b_k + kofs;
                uint32_t t0, t1, t2, t3;
                LDSM_X4(t0, t1, t2, t3, addr);
                bh[2 * np][0] = t0; bh[2 * np][1] = t1;
                bh[2 * np + 1][0] = t2; bh[2 * np + 1][1] = t3;
                LDSM_X4(t0, t1, t2, t3, addr + BT_B);
                bl[2 * np][0] = t0; bl[2 * np][1] = t1;
                bl[2 * np + 1][0] = t2; bl[2 * np + 1][1] = t3;
            }
            #pragma unroll
            for (int mf = 0; mf < 2; mf++)
                #pragma unroll
                for (int nf = 0; nf < 4; nf++) {
                    MMA_BF16(acc[mf][nf], ah[mf], bh[nf]);
                    MMA_BF16(acc[mf][nf], ah[mf], bl[nf]);
                    MMA_BF16(acc[mf][nf], al[mf], bh[nf]);
                }
        }
        __syncthreads();
    }

    int rr = m_blk + wm * 32 + (lane >> 2);
    int cc = n_blk + wn * 32 + 2 * (lane & 3);
    #pragma unroll
    for (int mf = 0; mf < 2; mf++)
        #pragma unroll
        for (int nf = 0; nf < 4; nf++) {
            float* d0 = g_P1 + (size_t)(rr + mf * 16) * NHID + cc + nf * 8;
            float* d1 = g_P1 + (size_t)(rr + mf * 16 + 8) * NHID + cc + nf * 8;
            *reinterpret_cast<float2*>(d0) = make_float2(acc[mf][nf][0], acc[mf][nf][1]);
            *reinterpret_cast<float2*>(d1) = make_float2(acc[mf][nf][2], acc[mf][nf][3]);
        }
}

// ---------------------------------------------------------------------------
// Kernel 3 (fused spmm_relu + gemm2): P2 = relu(norm_adj @ P1) @ W2.
// Only change: P2 writes use padded stride P2LD.
// ---------------------------------------------------------------------------
__global__ __launch_bounds__(256) void spmm_gemm2() {
    int row = blockIdx.x;
    int t   = threadIdx.x;
    __shared__ int   snbr[CAP];
    __shared__ float sd[CAP];
    __shared__ float sh[NHID];

    int cnt = g_cnt[row];
    if (t < cnt) { int j = g_nbr[row * CAP + t]; snbr[t] = j; sd[t] = g_d[j]; }
    __syncthreads();

    float di  = g_d[row];
    float acc = di * g_P1[(size_t)row * NHID + t];
    for (int k = 0; k < cnt; k++)
        acc += sd[k] * g_P1[(size_t)snbr[k] * NHID + t];
    sh[t] = fmaxf(di * acc, 0.f);
    __syncthreads();

    int w = t >> 5, lane = t & 31;
    #pragma unroll
    for (int i = 0; i < 5; i++) {
        int c = w + 8 * i;                        // 0..39
        const float* wr = g_W2T + (size_t)c * NHID;
        float a = 0.f;
        #pragma unroll
        for (int k = lane; k < NHID; k += 32)
            a += sh[k] * wr[k];
        #pragma unroll
        for (int o = 16; o; o >>= 1)
            a += __shfl_xor_sync(0xffffffffu, a, o);
        if (lane == 0)
            g_P2[(size_t)row * P2LD + c] = a;
    }
}

// ---------------------------------------------------------------------------
// Kernel 4: out = log_softmax( relu( norm_adj @ P2 ) ). One warp per row.
// R13: neighbor indices AND degrees preloaded into registers (coalesced),
// distributed via shfl -> mainloop is pure independent P2 loads (MLP=4);
// P2 rows padded to 256B so each lane-load is one aligned 128B line.
// ---------------------------------------------------------------------------
__global__ __launch_bounds__(256) void spmm2_out(float* __restrict__ out) {
    const unsigned FULL = 0xffffffffu;
    int warp = threadIdx.x >> 5;
    int lane = threadIdx.x & 31;
    int row  = blockIdx.x * 8 + warp;

    int   cnt = g_cnt[row];
    float di  = g_d[row];
    const int* nrow = g_nbr + row * CAP;

    // coalesced preload of all neighbor idx + degree into registers
    int   idxA = (lane < cnt) ? nrow[lane] : 0;
    float dgA  = (lane < cnt) ? g_d[idxA] : 0.f;
    int   cnt2 = cnt - 32;                         // rarely > 0
    int   idxB = (lane < cnt2) ? nrow[32 + lane] : 0;
    float dgB  = (lane < cnt2) ? g_d[idxB] : 0.f;

    bool hi = (lane < NCLASS - 32);                // lane < 8
    const float* p2r = g_P2 + (size_t)row * P2LD;
    float a0 = di * p2r[lane];
    float a1 = hi ? di * p2r[32 + lane] : 0.f;
    float b0 = 0.f, b1 = 0.f, c0 = 0.f, c1 = 0.f, e0 = 0.f, e1 = 0.f;

    int kmax = (cnt < 32) ? cnt : 32;
    int k = 0;
    for (; k + 3 < kmax; k += 4) {                 // 4 independent row-loads
        int   j0 = __shfl_sync(FULL, idxA, k),     j1 = __shfl_sync(FULL, idxA, k + 1);
        int   j2 = __shfl_sync(FULL, idxA, k + 2), j3 = __shfl_sync(FULL, idxA, k + 3);
        float w0 = __shfl_sync(FULL, dgA, k),      w1 = __shfl_sync(FULL, dgA, k + 1);
        float w2 = __shfl_sync(FULL, dgA, k + 2),  w3 = __shfl_sync(FULL, dgA, k + 3);
        const float* q0 = g_P2 + (size_t)j0 * P2LD;
        const float* q1 = g_P2 + (size_t)j1 * P2LD;
        const float* q2 = g_P2 + (size_t)j2 * P2LD;
        const float* q3 = g_P2 + (size_t)j3 * P2LD;
        a0 += w0 * q0[lane]; b0 += w1 * q1[lane];
        c0 += w2 * q2[lane]; e0 += w3 * q3[lane];
        if (hi) {
            a1 += w0 * q0[32 + lane]; b1 += w1 * q1[32 + lane];
            c1 += w2 * q2[32 + lane]; e1 += w3 * q3[32 + lane];
        }
    }
    for (; k < kmax; k++) {
        int   j = __shfl_sync(FULL, idxA, k);
        float w = __shfl_sync(FULL, dgA, k);
        const float* q = g_P2 + (size_t)j * P2LD;
        a0 += w * q[lane];
        if (hi) a1 += w * q[32 + lane];
    }
    for (k = 0; k < cnt2; k++) {
        int   j = __shfl_sync(FULL, idxB, k);
        float w = __shfl_sync(FULL, dgB, k);
        const float* q = g_P2 + (size_t)j * P2LD;
        a0 += w * q[lane];
        if (hi) a1 += w * q[32 + lane];
    }

    float v0 = fmaxf(di * ((a0 + b0) + (c0 + e0)), 0.f);
    float v1 = hi ? fmaxf(di * ((a1 + b1) + (c1 + e1)), 0.f) : -1e30f;

    float m = fmaxf(v0, v1);
    #pragma unroll
    for (int o = 16; o; o >>= 1) m = fmaxf(m, __shfl_xor_sync(FULL, m, o));

    float s = expf(v0 - m) + (hi ? expf(v1 - m) : 0.f);
    #pragma unroll
    for (int o = 16; o; o >>= 1) s += __shfl_xor_sync(FULL, s, o);

    float ls = m + logf(s);
    float* orow = out + (size_t)row * NCLASS;
    orow[lane] = v0 - ls;
    if (hi) orow[32 + lane] = v1 - ls;
}

// ---------------------------------------------------------------------------
extern "C" void kernel_launch(void* const* d_in, const int* in_sizes, int n_in,
                              void* d_out, int out_size) {
    const float* x   = (const float*)d_in[0];   // [8192, 512]
    const float* adj = (const float*)d_in[1];   // [8192, 8192]
    const float* W1  = (const float*)d_in[2];   // [512, 256]
    const float* W2  = (const float*)d_in[3];   // [256, 40]
    float* out = (float*)d_out;                 // [8192, 40]

    cudaFuncSetAttribute(mma_gemm1, cudaFuncAttributeMaxDynamicSharedMemorySize, SMEM_MMA);

    prep_fused<<<PREP_BLOCKS, 256>>>(adj, x, W1, W2);
    mma_gemm1<<<dim3(NHID / 128, N_NODES / 64), 256, SMEM_MMA>>>();
    spmm_gemm2<<<N_NODES, 256>>>();
    spmm2_out<<<N_NODES / 8, 256>>>(out);
}